// round 13
// baseline (speedup 1.0000x reference)
#include <cuda_runtime.h>
#include <math.h>

#define N_NODES 20000
#define F_IN    512
#define HDIM    64
#define L_LAYERS 8
#define E_EDGES 640000
#define C_OUT   40
#define NPAIR   2080          // 64*65/2 pairs (i<=j)
#define APR     96            // padded A row: 8 kg * 12 floats (10 used, 16B-aligned)

typedef unsigned long long ull_t;

// ---------------- device scratch (no runtime allocation allowed) ----------------
// g_cnt relies on (a) module-load zero-init for the first run and (b) scan_kernel
// re-zeroing it at the end of every run -> deterministic across graph replays.
__device__ float g_h0[N_NODES * HDIM];
__device__ float g_hA[N_NODES * HDIM];
__device__ float g_hB[N_NODES * HDIM];
__device__ int   g_cnt[N_NODES];
__device__ int   g_ptr[N_NODES + 1];
__device__ int   g_cursor[N_NODES];
__device__ int2  g_edges[E_EDGES];            // x = col index, y = float bits of weight
__device__ int   g_pi[NPAIR];
__device__ int   g_pj[NPAIR];
__device__ float g_Apack[NPAIR * APR];        // [p][kg][12]: 5 duplicated k-pairs + pad
__device__ float g_diag[N_NODES * C_OUT];     // sink for the diagnostic final launch

#define FMA_F32X2(d, a, b, c) \
    asm("fma.rn.f32x2 %0, %1, %2, %3;" : "=l"(d) : "l"(a), "l"(b), "l"(c))

__device__ __forceinline__ ull_t pack2(float lo, float hi) {
    ull_t r;
    asm("mov.b64 %0, {%1, %2};" : "=l"(r) : "f"(lo), "f"(hi));
    return r;
}

// ---------------- hist (+ pair-table init folded in) ----------------
__global__ void hist_kernel(const int* __restrict__ row) {
    int e = blockIdx.x * blockDim.x + threadIdx.x;
    if (e < E_EDGES) atomicAdd(&g_cnt[row[e]], 1);
    if (e < NPAIR) {
        int i = 0, off = 0;
        while (off + (HDIM - i) <= e) { off += HDIM - i; i++; }
        g_pi[e] = i;
        g_pj[e] = i + (e - off);
    }
}

// single-block exclusive scan over 20000 counters -> g_ptr, g_cursor; resets g_cnt
__global__ void scan_kernel() {
    const int T = 1024;
    const int PER = (N_NODES + T - 1) / T;  // 20
    __shared__ int sums[T];
    int t = threadIdx.x;
    int base = t * PER;
    int local[PER];
    int s = 0;
#pragma unroll
    for (int i = 0; i < PER; i++) {
        int idx = base + i;
        int v = (idx < N_NODES) ? g_cnt[idx] : 0;
        if (idx < N_NODES) g_cnt[idx] = 0;   // reset for next replay
        local[i] = s;
        s += v;
    }
    sums[t] = s;
    __syncthreads();
    for (int off = 1; off < T; off <<= 1) {
        int v = (t >= off) ? sums[t - off] : 0;
        __syncthreads();
        sums[t] += v;
        __syncthreads();
    }
    int offset = (t == 0) ? 0 : sums[t - 1];
#pragma unroll
    for (int i = 0; i < PER; i++) {
        int idx = base + i;
        if (idx < N_NODES) {
            int p = offset + local[i];
            g_ptr[idx] = p;
            g_cursor[idx] = p;
        }
    }
    if (t == T - 1) g_ptr[N_NODES] = sums[T - 1];
}

// ---------------- fused scatter + lin0 (disjoint block ranges) ----------------
#define SC_BLOCKS ((E_EDGES + 511) / 512)      // 1250
#define L0_RT 144
#define L0_BLOCKS ((N_NODES + L0_RT - 1) / L0_RT)  // 139
#define L0_XS 149
#define L0_XSZ (32 * L0_XS)
#define L0_WSZ (32 * 64)
#define L0_SMEM_FLOATS (2 * L0_XSZ + 2 * L0_WSZ)
#define L0_SMEM_BYTES  (L0_SMEM_FLOATS * 4)

__global__ void fused_scatter_lin0(const int* __restrict__ row, const int* __restrict__ col,
                                   const float* __restrict__ ew,
                                   const float* __restrict__ x, const float* __restrict__ w,
                                   const float* __restrict__ b) {
    if (blockIdx.x < SC_BLOCKS) {
        int e = blockIdx.x * 512 + threadIdx.x;
        if (e < E_EDGES) {
            int r = row[e];
            int pos = atomicAdd(&g_cursor[r], 1);
            g_edges[pos] = make_int2(col[e], __float_as_int(ew[e]));
        }
        return;
    }
    // ---- lin0 part (K-split x2, prefetch pipelined) ----
    extern __shared__ float sm[];
    int tid = threadIdx.x;
    int kh = tid >> 8;
    int t  = tid & 255;
    int tx = t & 15;
    int ty = t >> 4;
    float* Xs = sm + kh * L0_XSZ;
    float* Ws = sm + 2 * L0_XSZ + kh * L0_WSZ;
    int row0 = (blockIdx.x - SC_BLOCKS) * L0_RT;
    int kbase = kh * 256;

    ull_t acc0[9], acc1[9];
#pragma unroll
    for (int m = 0; m < 9; m++) { acc0[m] = 0ull; acc1[m] = 0ull; }

    float4 xv[5];
    float4 wv[2];
    int xr[5], xk4[5];
    bool xok[5];
#pragma unroll
    for (int q = 0; q < 5; q++) {
        int idx = t + 256 * q;
        xok[q] = (idx < L0_RT * 8);
        xr[q] = idx >> 3;
        xk4[q] = idx & 7;
    }
    int wkk[2], wc4[2];
#pragma unroll
    for (int q = 0; q < 2; q++) {
        int idx = t + 256 * q;
        wkk[q] = idx >> 4;
        wc4[q] = idx & 15;
    }

#pragma unroll
    for (int q = 0; q < 5; q++) {
        xv[q] = make_float4(0.f, 0.f, 0.f, 0.f);
        if (xok[q]) {
            int gr = row0 + xr[q];
            if (gr < N_NODES) xv[q] = *(const float4*)&x[gr * F_IN + kbase + xk4[q] * 4];
        }
    }
#pragma unroll
    for (int q = 0; q < 2; q++)
        wv[q] = *(const float4*)&w[(kbase + wkk[q]) * HDIM + wc4[q] * 4];

    for (int c = 0; c < 8; c++) {
        __syncthreads();
#pragma unroll
        for (int q = 0; q < 5; q++) {
            if (xok[q]) {
                int r = xr[q], k4 = xk4[q];
                Xs[(k4 * 4 + 0) * L0_XS + r] = xv[q].x;
                Xs[(k4 * 4 + 1) * L0_XS + r] = xv[q].y;
                Xs[(k4 * 4 + 2) * L0_XS + r] = xv[q].z;
                Xs[(k4 * 4 + 3) * L0_XS + r] = xv[q].w;
            }
        }
#pragma unroll
        for (int q = 0; q < 2; q++)
            *(float4*)&Ws[wkk[q] * 64 + wc4[q] * 4] = wv[q];
        __syncthreads();

        if (c + 1 < 8) {
            int k0 = kbase + (c + 1) * 32;
#pragma unroll
            for (int q = 0; q < 5; q++) {
                if (xok[q]) {
                    int gr = row0 + xr[q];
                    if (gr < N_NODES)
                        xv[q] = *(const float4*)&x[gr * F_IN + k0 + xk4[q] * 4];
                }
            }
#pragma unroll
            for (int q = 0; q < 2; q++)
                wv[q] = *(const float4*)&w[(k0 + wkk[q]) * HDIM + wc4[q] * 4];
        }

#pragma unroll
        for (int kk = 0; kk < 32; kk++) {
            double2 bd = *(const double2*)&Ws[kk * 64 + tx * 4];
            ull_t b01 = __double_as_longlong(bd.x);
            ull_t b23 = __double_as_longlong(bd.y);
#pragma unroll
            for (int m = 0; m < 9; m++) {
                float a = Xs[kk * L0_XS + ty * 9 + m];
                ull_t pa = pack2(a, a);
                FMA_F32X2(acc0[m], pa, b01, acc0[m]);
                FMA_F32X2(acc1[m], pa, b23, acc1[m]);
            }
        }
    }

    __syncthreads();
    float* part = sm;
    if (kh == 1) {
#pragma unroll
        for (int m = 0; m < 9; m++) {
            float4 v;
            v.x = __uint_as_float((unsigned)(acc0[m] & 0xffffffffull));
            v.y = __uint_as_float((unsigned)(acc0[m] >> 32));
            v.z = __uint_as_float((unsigned)(acc1[m] & 0xffffffffull));
            v.w = __uint_as_float((unsigned)(acc1[m] >> 32));
            *(float4*)&part[t * 36 + m * 4] = v;
        }
    }
    __syncthreads();
    if (kh == 0) {
        float4 bv = *(const float4*)&b[tx * 4];
#pragma unroll
        for (int m = 0; m < 9; m++) {
            int gr = row0 + ty * 9 + m;
            if (gr < N_NODES) {
                float4 p = *(const float4*)&part[t * 36 + m * 4];
                float4 r;
                r.x = fmaxf(__uint_as_float((unsigned)(acc0[m] & 0xffffffffull)) + p.x + bv.x, 0.f);
                r.y = fmaxf(__uint_as_float((unsigned)(acc0[m] >> 32)) + p.y + bv.y, 0.f);
                r.z = fmaxf(__uint_as_float((unsigned)(acc1[m] & 0xffffffffull)) + p.z + bv.z, 0.f);
                r.w = fmaxf(__uint_as_float((unsigned)(acc1[m] >> 32)) + p.w + bv.w, 0.f);
                *(float4*)&g_h0[gr * HDIM + tx * 4] = r;
                *(float4*)&g_hA[gr * HDIM + tx * 4] = r;
            }
        }
    }
}

// A[p][k] = W[(i,j),k] + (i!=j ? W[(j,i),k] : 0), duplicated pairs, padded layout
__global__ void apack_kernel(const float* __restrict__ lin1_w) {
    int idx = blockIdx.x * blockDim.x + threadIdx.x;
    if (idx < NPAIR * C_OUT) {
        int p = idx / C_OUT;
        int k = idx % C_OUT;
        int i = g_pi[p], j = g_pj[p];
        float v = lin1_w[(i * HDIM + j) * C_OUT + k];
        if (i != j) v += lin1_w[(j * HDIM + i) * C_OUT + k];
        int kg = k / 5, kc = k % 5;
        float* dst = &g_Apack[p * APR + kg * 12 + kc * 2];
        dst[0] = v;
        dst[1] = v;
    }
}

// ---------------- fused GCN2 layer (R8/R12 measured-best: float2 gathers, 8-edge MLP) -------
// one warp per node; lane owns columns 2*lane, 2*lane+1.
__global__ void layer_kernel(const float* __restrict__ hin, float* __restrict__ hout,
                             const float* __restrict__ convw, float one_minus_beta, float beta) {
    __shared__ float Wc[64][64];
    int tid = threadIdx.x;
#pragma unroll
    for (int q = 0; q < 4; q++) {
        int idx = tid + 256 * q;
        *(float4*)&Wc[0][idx * 4] = *(const float4*)&convw[idx * 4];
    }
    __syncthreads();

    int warp = tid >> 5, lane = tid & 31;
    int node = blockIdx.x * 8 + warp;
    if (node >= N_NODES) return;

    int s = g_ptr[node];
    int e = g_ptr[node + 1];
    float acc0 = 0.f, acc1 = 0.f;
    int i = s;
    if ((i & 1) && i < e) {
        int2 a0 = g_edges[i];
        float wv = __int_as_float(a0.y);
        float2 v = __ldg((const float2*)&hin[a0.x * HDIM + 2 * lane]);
        acc0 = fmaf(wv, v.x, acc0);
        acc1 = fmaf(wv, v.y, acc1);
        i++;
    }
    for (; i + 8 <= e; i += 8) {
        int4 e01 = *(const int4*)&g_edges[i];
        int4 e23 = *(const int4*)&g_edges[i + 2];
        int4 e45 = *(const int4*)&g_edges[i + 4];
        int4 e67 = *(const int4*)&g_edges[i + 6];
        float2 v0 = __ldg((const float2*)&hin[e01.x * HDIM + 2 * lane]);
        float2 v1 = __ldg((const float2*)&hin[e01.z * HDIM + 2 * lane]);
        float2 v2 = __ldg((const float2*)&hin[e23.x * HDIM + 2 * lane]);
        float2 v3 = __ldg((const float2*)&hin[e23.z * HDIM + 2 * lane]);
        float2 v4 = __ldg((const float2*)&hin[e45.x * HDIM + 2 * lane]);
        float2 v5 = __ldg((const float2*)&hin[e45.z * HDIM + 2 * lane]);
        float2 v6 = __ldg((const float2*)&hin[e67.x * HDIM + 2 * lane]);
        float2 v7 = __ldg((const float2*)&hin[e67.z * HDIM + 2 * lane]);
        acc0 = fmaf(__int_as_float(e01.y), v0.x, acc0);
        acc1 = fmaf(__int_as_float(e01.y), v0.y, acc1);
        acc0 = fmaf(__int_as_float(e01.w), v1.x, acc0);
        acc1 = fmaf(__int_as_float(e01.w), v1.y, acc1);
        acc0 = fmaf(__int_as_float(e23.y), v2.x, acc0);
        acc1 = fmaf(__int_as_float(e23.y), v2.y, acc1);
        acc0 = fmaf(__int_as_float(e23.w), v3.x, acc0);
        acc1 = fmaf(__int_as_float(e23.w), v3.y, acc1);
        acc0 = fmaf(__int_as_float(e45.y), v4.x, acc0);
        acc1 = fmaf(__int_as_float(e45.y), v4.y, acc1);
        acc0 = fmaf(__int_as_float(e45.w), v5.x, acc0);
        acc1 = fmaf(__int_as_float(e45.w), v5.y, acc1);
        acc0 = fmaf(__int_as_float(e67.y), v6.x, acc0);
        acc1 = fmaf(__int_as_float(e67.y), v6.y, acc1);
        acc0 = fmaf(__int_as_float(e67.w), v7.x, acc0);
        acc1 = fmaf(__int_as_float(e67.w), v7.y, acc1);
    }
    for (; i + 4 <= e; i += 4) {
        int4 e01 = *(const int4*)&g_edges[i];
        int4 e23 = *(const int4*)&g_edges[i + 2];
        float2 v0 = __ldg((const float2*)&hin[e01.x * HDIM + 2 * lane]);
        float2 v1 = __ldg((const float2*)&hin[e01.z * HDIM + 2 * lane]);
        float2 v2 = __ldg((const float2*)&hin[e23.x * HDIM + 2 * lane]);
        float2 v3 = __ldg((const float2*)&hin[e23.z * HDIM + 2 * lane]);
        acc0 = fmaf(__int_as_float(e01.y), v0.x, acc0);
        acc1 = fmaf(__int_as_float(e01.y), v0.y, acc1);
        acc0 = fmaf(__int_as_float(e01.w), v1.x, acc0);
        acc1 = fmaf(__int_as_float(e01.w), v1.y, acc1);
        acc0 = fmaf(__int_as_float(e23.y), v2.x, acc0);
        acc1 = fmaf(__int_as_float(e23.y), v2.y, acc1);
        acc0 = fmaf(__int_as_float(e23.w), v3.x, acc0);
        acc1 = fmaf(__int_as_float(e23.w), v3.y, acc1);
    }
    for (; i < e; i++) {
        int2 a0 = g_edges[i];
        float wv = __int_as_float(a0.y);
        float2 v = __ldg((const float2*)&hin[a0.x * HDIM + 2 * lane]);
        acc0 = fmaf(wv, v.x, acc0);
        acc1 = fmaf(wv, v.y, acc1);
    }

    float2 h0v = *(const float2*)&g_h0[node * HDIM + 2 * lane];
    float o0 = 0.9f * acc0 + 0.1f * h0v.x;
    float o1 = 0.9f * acc1 + 0.1f * h0v.y;

    float gg0 = 0.f, gg1 = 0.f;
#pragma unroll
    for (int m = 0; m < 32; m++) {
        float om0 = __shfl_sync(0xffffffffu, o0, m);
        float om1 = __shfl_sync(0xffffffffu, o1, m);
        float2 w0 = *(const float2*)&Wc[2 * m][2 * lane];
        float2 w1 = *(const float2*)&Wc[2 * m + 1][2 * lane];
        gg0 = fmaf(om0, w0.x, gg0);
        gg1 = fmaf(om0, w0.y, gg1);
        gg0 = fmaf(om1, w1.x, gg0);
        gg1 = fmaf(om1, w1.y, gg1);
    }
    float2 r;
    r.x = fmaxf(one_minus_beta * o0 + beta * gg0, 0.f);
    r.y = fmaxf(one_minus_beta * o1 + beta * gg1, 0.f);
    *(float2*)&hout[node * HDIM + 2 * lane] = r;
}

// ---------------- final v2: pair-chunk K-split x2 (R12 version, unchanged) ----------------
#define FM 64
#define FTHR 256
#define KC 32
#define NCHUNK_TOT 65
#define NCHUNK_HALF 33
#define OFF_P   0                            // 2 x [KC][64]  = 4096
#define OFF_A   (OFF_P + 2 * KC * FM)        // 2 x [KC][APR] = 6144
#define OFF_H   (OFF_A + 2 * KC * APR)       // [64][65] = 4160
#define OFF_N2  (OFF_H + FM * 65)            // 64
#define FK_SMEM_FLOATS (OFF_N2 + FM)         // 14464 floats = 57856 B
#define FK_SMEM_BYTES  (FK_SMEM_FLOATS * 4)

__global__ void final_kernel(const float* __restrict__ hin, const float* __restrict__ b1,
                             float* __restrict__ out) {
    extern __shared__ float smem[];
    float* hs  = smem + OFF_H;
    float* n2s = smem + OFF_N2;

    int tid = threadIdx.x;
    int kh = tid >> 7;
    int t  = tid & 127;
    float* Pt = smem + OFF_P + kh * (KC * FM);
    float* At = smem + OFF_A + kh * (KC * APR);
    int n0 = blockIdx.x * FM;

#pragma unroll
    for (int q = 0; q < 4; q++) {
        int idx = tid + FTHR * q;
        int nd = idx >> 4;
        int j4 = idx & 15;
        int gn = n0 + nd;
        float4 v = make_float4(0.f, 0.f, 0.f, 0.f);
        if (gn < N_NODES) v = *(const float4*)&hin[gn * HDIM + j4 * 4];
        float* hr = hs + nd * 65 + j4 * 4;
        hr[0] = v.x; hr[1] = v.y; hr[2] = v.z; hr[3] = v.w;
    }
    __syncthreads();

    if (tid < FM) {
        float s = 0.f;
        const float* hr = hs + tid * 65;
#pragma unroll
        for (int j = 0; j < 64; j++) s = fmaf(hr[j], hr[j], s);
        n2s[tid] = s;
    }

    int g = t >> 3;
    int kg = t & 7;
    int kbase = kg * 5;

    ull_t acc0[5], acc1[5];
#pragma unroll
    for (int c = 0; c < 5; c++) { acc0[c] = 0ull; acc1[c] = 0ull; }

    for (int ci = 0; ci < NCHUNK_HALF; ci++) {
        int chunk = ci * 2 + kh;
        bool active = (chunk < NCHUNK_TOT);
        int pc = chunk * KC;
        __syncthreads();
        if (active) {
            const float4* src = (const float4*)&g_Apack[pc * APR];
#pragma unroll
            for (int q = 0; q < KC * APR / 4 / 128; q++) {
                int v = t + 128 * q;
                *(float4*)&At[v * 4] = src[v];
            }
#pragma unroll
            for (int q = 0; q < KC * FM / 128; q++) {
                int tt = t + 128 * q;
                int pl = tt >> 6;
                int nd = tt & 63;
                int p = pc + pl;
                int i = __ldg(&g_pi[p]);
                int j = __ldg(&g_pj[p]);
                Pt[pl * FM + nd] = hs[nd * 65 + i] * hs[nd * 65 + j];
            }
        }
        __syncthreads();
        if (active) {
#pragma unroll 4
            for (int kk = 0; kk < KC; kk++) {
                double2 pd = *(const double2*)&Pt[kk * FM + g * 4];
                ull_t p01 = __double_as_longlong(pd.x);
                ull_t p23 = __double_as_longlong(pd.y);
                const float* arow = At + kk * APR + kg * 12;
                double2 a01 = *(const double2*)arow;
                double2 a23 = *(const double2*)(arow + 4);
                ull_t a4 = *(const ull_t*)(arow + 8);
                ull_t a0 = __double_as_longlong(a01.x);
                ull_t a1 = __double_as_longlong(a01.y);
                ull_t a2 = __double_as_longlong(a23.x);
                ull_t a3 = __double_as_longlong(a23.y);
                FMA_F32X2(acc0[0], p01, a0, acc0[0]);
                FMA_F32X2(acc1[0], p23, a0, acc1[0]);
                FMA_F32X2(acc0[1], p01, a1, acc0[1]);
                FMA_F32X2(acc1[1], p23, a1, acc1[1]);
                FMA_F32X2(acc0[2], p01, a2, acc0[2]);
                FMA_F32X2(acc1[2], p23, a2, acc1[2]);
                FMA_F32X2(acc0[3], p01, a3, acc0[3]);
                FMA_F32X2(acc1[3], p23, a3, acc1[3]);
                FMA_F32X2(acc0[4], p01, a4, acc0[4]);
                FMA_F32X2(acc1[4], p23, a4, acc1[4]);
            }
        }
    }
    __syncthreads();

    float* zsh = smem + OFF_P + kh * (FM * C_OUT);
#pragma unroll
    for (int c = 0; c < 5; c++) {
        int k = kbase + c;
        zsh[(g * 4 + 0) * C_OUT + k] = __uint_as_float((unsigned)(acc0[c] & 0xffffffffull));
        zsh[(g * 4 + 1) * C_OUT + k] = __uint_as_float((unsigned)(acc0[c] >> 32));
        zsh[(g * 4 + 2) * C_OUT + k] = __uint_as_float((unsigned)(acc1[c] & 0xffffffffull));
        zsh[(g * 4 + 3) * C_OUT + k] = __uint_as_float((unsigned)(acc1[c] >> 32));
    }
    __syncthreads();

    if (tid < FM) {
        int gn = n0 + tid;
        if (gn < N_NODES) {
            const float* zs0 = smem + OFF_P;
            const float* zs1 = smem + OFF_P + FM * C_OUT;
            const float MAXN = 1.0f - 4e-3f;
            float n2 = fmaxf(n2s[tid], 1e-15f);
            float pn = fminf(n2, MAXN);
            float tt = atanhf(pn);
            float scale = tt / n2;

            float u[C_OUT];
            float un2 = 0.f;
#pragma unroll
            for (int k = 0; k < C_OUT; k++) {
                float z = zs0[tid * C_OUT + k] + zs1[tid * C_OUT + k];
                float v = scale * z + b1[k];
                u[k] = v;
                un2 = fmaf(v, v, un2);
            }
            float un = fmaxf(sqrtf(un2), 1e-15f);
            float th = tanhf(un);
            float gsc = fminf(th, MAXN) / un;

            float m = -INFINITY;
#pragma unroll
            for (int k = 0; k < C_OUT; k++) {
                u[k] *= gsc;
                m = fmaxf(m, u[k]);
            }
            float se = 0.f;
#pragma unroll
            for (int k = 0; k < C_OUT; k++) se += expf(u[k] - m);
            float lse = m + logf(se);
#pragma unroll
            for (int k = 0; k < C_OUT; k++) out[gn * C_OUT + k] = u[k] - lse;
        }
    }
}

// ---------------- launch ----------------
// DIAGNOSTIC ROUND: a copy of final_kernel runs 4th (the ncu-profiled slot),
// reading g_hA (= h0, valid data at that point) and writing to g_diag (scratch).
// Deterministic and side-effect-free on the real output; costs +F runtime but
// yields final_kernel's first real ncu roofline.
extern "C" void kernel_launch(void* const* d_in, const int* in_sizes, int n_in,
                              void* d_out, int out_size) {
    const float* x      = (const float*)d_in[0];
    const int*   row    = (const int*)d_in[1];
    const int*   col    = (const int*)d_in[2];
    const float* ew     = (const float*)d_in[3];
    const float* lin0_w = (const float*)d_in[4];
    const float* lin0_b = (const float*)d_in[5];
    const float* conv_w = (const float*)d_in[6];
    const float* lin1_w = (const float*)d_in[7];
    const float* lin1_b = (const float*)d_in[8];
    float* out = (float*)d_out;

    float* hA = nullptr;
    float* hB = nullptr;
    float* diag = nullptr;
    cudaGetSymbolAddress((void**)&hA, g_hA);
    cudaGetSymbolAddress((void**)&hB, g_hB);
    cudaGetSymbolAddress((void**)&diag, g_diag);

    cudaFuncSetAttribute(fused_scatter_lin0, cudaFuncAttributeMaxDynamicSharedMemorySize,
                         L0_SMEM_BYTES);
    cudaFuncSetAttribute(final_kernel, cudaFuncAttributeMaxDynamicSharedMemorySize,
                         FK_SMEM_BYTES);

    hist_kernel<<<(E_EDGES + 255) / 256, 256>>>(row);                       // 1
    scan_kernel<<<1, 1024>>>();                                             // 2
    fused_scatter_lin0<<<SC_BLOCKS + L0_BLOCKS, 512, L0_SMEM_BYTES>>>(
        row, col, ew, x, lin0_w, lin0_b);                                   // 3
    final_kernel<<<(N_NODES + FM - 1) / FM, FTHR, FK_SMEM_BYTES>>>(
        hA, lin1_b, diag);                                                  // 4 <- profiled (diagnostic)
    apack_kernel<<<(NPAIR * C_OUT + 255) / 256, 256>>>(lin1_w);             // 5

    const float* hin = hA;
    float* hout = hB;
    for (int l = 0; l < L_LAYERS; l++) {
        float beta = logf(0.5f / (float)(l + 1) + 1.0f);
        layer_kernel<<<(N_NODES + 7) / 8, 256>>>(hin, hout, conv_w + l * HDIM * HDIM,
                                                 1.0f - beta, beta);
        const float* tmp = hin; hin = hout; hout = (float*)tmp;
    }

    final_kernel<<<(N_NODES + FM - 1) / FM, FTHR, FK_SMEM_BYTES>>>(hin, lin1_b, out);
}

// round 14
// speedup vs baseline: 1.5147x; 1.5147x over previous
#include <cuda_runtime.h>
#include <math.h>

#define N_NODES 20000
#define F_IN    512
#define HDIM    64
#define L_LAYERS 8
#define E_EDGES 640000
#define C_OUT   40
#define NPAIR   2080          // 64*65/2 pairs (i<=j)

typedef unsigned long long ull_t;

// ---------------- device scratch (no runtime allocation allowed) ----------------
__device__ float g_h0[N_NODES * HDIM];
__device__ float g_hA[N_NODES * HDIM];
__device__ float g_hB[N_NODES * HDIM];
__device__ int   g_cnt[N_NODES];
__device__ int   g_ptr[N_NODES + 1];
__device__ int   g_cursor[N_NODES];
__device__ int2  g_edges[E_EDGES];            // x = col index, y = float bits of weight
__device__ int   g_pi[NPAIR];
__device__ int   g_pj[NPAIR];
__device__ float g_A2[NPAIR * C_OUT];         // compact symmetric-pair weights [p][k]

#define FMA_F32X2(d, a, b, c) \
    asm("fma.rn.f32x2 %0, %1, %2, %3;" : "=l"(d) : "l"(a), "l"(b), "l"(c))

__device__ __forceinline__ ull_t pack2(float lo, float hi) {
    ull_t r;
    asm("mov.b64 %0, {%1, %2};" : "=l"(r) : "f"(lo), "f"(hi));
    return r;
}

// ---------------- hist (+ pair-table init folded in) ----------------
__global__ void hist_kernel(const int* __restrict__ row) {
    int e = blockIdx.x * blockDim.x + threadIdx.x;
    if (e < E_EDGES) atomicAdd(&g_cnt[row[e]], 1);
    if (e < NPAIR) {
        int i = 0, off = 0;
        while (off + (HDIM - i) <= e) { off += HDIM - i; i++; }
        g_pi[e] = i;
        g_pj[e] = i + (e - off);
    }
}

// single-block exclusive scan over 20000 counters -> g_ptr, g_cursor; resets g_cnt
__global__ void scan_kernel() {
    const int T = 1024;
    const int PER = (N_NODES + T - 1) / T;  // 20
    __shared__ int sums[T];
    int t = threadIdx.x;
    int base = t * PER;
    int local[PER];
    int s = 0;
#pragma unroll
    for (int i = 0; i < PER; i++) {
        int idx = base + i;
        int v = (idx < N_NODES) ? g_cnt[idx] : 0;
        if (idx < N_NODES) g_cnt[idx] = 0;
        local[i] = s;
        s += v;
    }
    sums[t] = s;
    __syncthreads();
    for (int off = 1; off < T; off <<= 1) {
        int v = (t >= off) ? sums[t - off] : 0;
        __syncthreads();
        sums[t] += v;
        __syncthreads();
    }
    int offset = (t == 0) ? 0 : sums[t - 1];
#pragma unroll
    for (int i = 0; i < PER; i++) {
        int idx = base + i;
        if (idx < N_NODES) {
            int p = offset + local[i];
            g_ptr[idx] = p;
            g_cursor[idx] = p;
        }
    }
    if (t == T - 1) g_ptr[N_NODES] = sums[T - 1];
}

// ---------------- fused scatter + lin0 (disjoint block ranges) ----------------
#define SC_BLOCKS ((E_EDGES + 511) / 512)      // 1250
#define L0_RT 144
#define L0_BLOCKS ((N_NODES + L0_RT - 1) / L0_RT)  // 139
#define L0_XS 149
#define L0_XSZ (32 * L0_XS)
#define L0_WSZ (32 * 64)
#define L0_SMEM_FLOATS (2 * L0_XSZ + 2 * L0_WSZ)
#define L0_SMEM_BYTES  (L0_SMEM_FLOATS * 4)

__global__ void fused_scatter_lin0(const int* __restrict__ row, const int* __restrict__ col,
                                   const float* __restrict__ ew,
                                   const float* __restrict__ x, const float* __restrict__ w,
                                   const float* __restrict__ b) {
    if (blockIdx.x < SC_BLOCKS) {
        int e = blockIdx.x * 512 + threadIdx.x;
        if (e < E_EDGES) {
            int r = row[e];
            int pos = atomicAdd(&g_cursor[r], 1);
            g_edges[pos] = make_int2(col[e], __float_as_int(ew[e]));
        }
        return;
    }
    extern __shared__ float sm[];
    int tid = threadIdx.x;
    int kh = tid >> 8;
    int t  = tid & 255;
    int tx = t & 15;
    int ty = t >> 4;
    float* Xs = sm + kh * L0_XSZ;
    float* Ws = sm + 2 * L0_XSZ + kh * L0_WSZ;
    int row0 = (blockIdx.x - SC_BLOCKS) * L0_RT;
    int kbase = kh * 256;

    ull_t acc0[9], acc1[9];
#pragma unroll
    for (int m = 0; m < 9; m++) { acc0[m] = 0ull; acc1[m] = 0ull; }

    float4 xv[5];
    float4 wv[2];
    int xr[5], xk4[5];
    bool xok[5];
#pragma unroll
    for (int q = 0; q < 5; q++) {
        int idx = t + 256 * q;
        xok[q] = (idx < L0_RT * 8);
        xr[q] = idx >> 3;
        xk4[q] = idx & 7;
    }
    int wkk[2], wc4[2];
#pragma unroll
    for (int q = 0; q < 2; q++) {
        int idx = t + 256 * q;
        wkk[q] = idx >> 4;
        wc4[q] = idx & 15;
    }

#pragma unroll
    for (int q = 0; q < 5; q++) {
        xv[q] = make_float4(0.f, 0.f, 0.f, 0.f);
        if (xok[q]) {
            int gr = row0 + xr[q];
            if (gr < N_NODES) xv[q] = *(const float4*)&x[gr * F_IN + kbase + xk4[q] * 4];
        }
    }
#pragma unroll
    for (int q = 0; q < 2; q++)
        wv[q] = *(const float4*)&w[(kbase + wkk[q]) * HDIM + wc4[q] * 4];

    for (int c = 0; c < 8; c++) {
        __syncthreads();
#pragma unroll
        for (int q = 0; q < 5; q++) {
            if (xok[q]) {
                int r = xr[q], k4 = xk4[q];
                Xs[(k4 * 4 + 0) * L0_XS + r] = xv[q].x;
                Xs[(k4 * 4 + 1) * L0_XS + r] = xv[q].y;
                Xs[(k4 * 4 + 2) * L0_XS + r] = xv[q].z;
                Xs[(k4 * 4 + 3) * L0_XS + r] = xv[q].w;
            }
        }
#pragma unroll
        for (int q = 0; q < 2; q++)
            *(float4*)&Ws[wkk[q] * 64 + wc4[q] * 4] = wv[q];
        __syncthreads();

        if (c + 1 < 8) {
            int k0 = kbase + (c + 1) * 32;
#pragma unroll
            for (int q = 0; q < 5; q++) {
                if (xok[q]) {
                    int gr = row0 + xr[q];
                    if (gr < N_NODES)
                        xv[q] = *(const float4*)&x[gr * F_IN + k0 + xk4[q] * 4];
                }
            }
#pragma unroll
            for (int q = 0; q < 2; q++)
                wv[q] = *(const float4*)&w[(k0 + wkk[q]) * HDIM + wc4[q] * 4];
        }

#pragma unroll
        for (int kk = 0; kk < 32; kk++) {
            double2 bd = *(const double2*)&Ws[kk * 64 + tx * 4];
            ull_t b01 = __double_as_longlong(bd.x);
            ull_t b23 = __double_as_longlong(bd.y);
#pragma unroll
            for (int m = 0; m < 9; m++) {
                float a = Xs[kk * L0_XS + ty * 9 + m];
                ull_t pa = pack2(a, a);
                FMA_F32X2(acc0[m], pa, b01, acc0[m]);
                FMA_F32X2(acc1[m], pa, b23, acc1[m]);
            }
        }
    }

    __syncthreads();
    float* part = sm;
    if (kh == 1) {
#pragma unroll
        for (int m = 0; m < 9; m++) {
            float4 v;
            v.x = __uint_as_float((unsigned)(acc0[m] & 0xffffffffull));
            v.y = __uint_as_float((unsigned)(acc0[m] >> 32));
            v.z = __uint_as_float((unsigned)(acc1[m] & 0xffffffffull));
            v.w = __uint_as_float((unsigned)(acc1[m] >> 32));
            *(float4*)&part[t * 36 + m * 4] = v;
        }
    }
    __syncthreads();
    if (kh == 0) {
        float4 bv = *(const float4*)&b[tx * 4];
#pragma unroll
        for (int m = 0; m < 9; m++) {
            int gr = row0 + ty * 9 + m;
            if (gr < N_NODES) {
                float4 p = *(const float4*)&part[t * 36 + m * 4];
                float4 r;
                r.x = fmaxf(__uint_as_float((unsigned)(acc0[m] & 0xffffffffull)) + p.x + bv.x, 0.f);
                r.y = fmaxf(__uint_as_float((unsigned)(acc0[m] >> 32)) + p.y + bv.y, 0.f);
                r.z = fmaxf(__uint_as_float((unsigned)(acc1[m] & 0xffffffffull)) + p.z + bv.z, 0.f);
                r.w = fmaxf(__uint_as_float((unsigned)(acc1[m] >> 32)) + p.w + bv.w, 0.f);
                *(float4*)&g_h0[gr * HDIM + tx * 4] = r;
                *(float4*)&g_hA[gr * HDIM + tx * 4] = r;
            }
        }
    }
}

// compact A: g_A2[p][k] = W[(i,j),k] + (i!=j ? W[(j,i),k] : 0)
__global__ void apack_kernel(const float* __restrict__ lin1_w) {
    int idx = blockIdx.x * blockDim.x + threadIdx.x;
    if (idx < NPAIR * C_OUT) {
        int p = idx / C_OUT;
        int k = idx % C_OUT;
        int i = g_pi[p], j = g_pj[p];
        float v = lin1_w[(i * HDIM + j) * C_OUT + k];
        if (i != j) v += lin1_w[(j * HDIM + i) * C_OUT + k];
        g_A2[p * C_OUT + k] = v;
    }
}

// ---------------- fused GCN2 layer (R8/R12 measured-best) ----------------
__global__ void layer_kernel(const float* __restrict__ hin, float* __restrict__ hout,
                             const float* __restrict__ convw, float one_minus_beta, float beta) {
    __shared__ float Wc[64][64];
    int tid = threadIdx.x;
#pragma unroll
    for (int q = 0; q < 4; q++) {
        int idx = tid + 256 * q;
        *(float4*)&Wc[0][idx * 4] = *(const float4*)&convw[idx * 4];
    }
    __syncthreads();

    int warp = tid >> 5, lane = tid & 31;
    int node = blockIdx.x * 8 + warp;
    if (node >= N_NODES) return;

    int s = g_ptr[node];
    int e = g_ptr[node + 1];
    float acc0 = 0.f, acc1 = 0.f;
    int i = s;
    if ((i & 1) && i < e) {
        int2 a0 = g_edges[i];
        float wv = __int_as_float(a0.y);
        float2 v = __ldg((const float2*)&hin[a0.x * HDIM + 2 * lane]);
        acc0 = fmaf(wv, v.x, acc0);
        acc1 = fmaf(wv, v.y, acc1);
        i++;
    }
    for (; i + 8 <= e; i += 8) {
        int4 e01 = *(const int4*)&g_edges[i];
        int4 e23 = *(const int4*)&g_edges[i + 2];
        int4 e45 = *(const int4*)&g_edges[i + 4];
        int4 e67 = *(const int4*)&g_edges[i + 6];
        float2 v0 = __ldg((const float2*)&hin[e01.x * HDIM + 2 * lane]);
        float2 v1 = __ldg((const float2*)&hin[e01.z * HDIM + 2 * lane]);
        float2 v2 = __ldg((const float2*)&hin[e23.x * HDIM + 2 * lane]);
        float2 v3 = __ldg((const float2*)&hin[e23.z * HDIM + 2 * lane]);
        float2 v4 = __ldg((const float2*)&hin[e45.x * HDIM + 2 * lane]);
        float2 v5 = __ldg((const float2*)&hin[e45.z * HDIM + 2 * lane]);
        float2 v6 = __ldg((const float2*)&hin[e67.x * HDIM + 2 * lane]);
        float2 v7 = __ldg((const float2*)&hin[e67.z * HDIM + 2 * lane]);
        acc0 = fmaf(__int_as_float(e01.y), v0.x, acc0);
        acc1 = fmaf(__int_as_float(e01.y), v0.y, acc1);
        acc0 = fmaf(__int_as_float(e01.w), v1.x, acc0);
        acc1 = fmaf(__int_as_float(e01.w), v1.y, acc1);
        acc0 = fmaf(__int_as_float(e23.y), v2.x, acc0);
        acc1 = fmaf(__int_as_float(e23.y), v2.y, acc1);
        acc0 = fmaf(__int_as_float(e23.w), v3.x, acc0);
        acc1 = fmaf(__int_as_float(e23.w), v3.y, acc1);
        acc0 = fmaf(__int_as_float(e45.y), v4.x, acc0);
        acc1 = fmaf(__int_as_float(e45.y), v4.y, acc1);
        acc0 = fmaf(__int_as_float(e45.w), v5.x, acc0);
        acc1 = fmaf(__int_as_float(e45.w), v5.y, acc1);
        acc0 = fmaf(__int_as_float(e67.y), v6.x, acc0);
        acc1 = fmaf(__int_as_float(e67.y), v6.y, acc1);
        acc0 = fmaf(__int_as_float(e67.w), v7.x, acc0);
        acc1 = fmaf(__int_as_float(e67.w), v7.y, acc1);
    }
    for (; i + 4 <= e; i += 4) {
        int4 e01 = *(const int4*)&g_edges[i];
        int4 e23 = *(const int4*)&g_edges[i + 2];
        float2 v0 = __ldg((const float2*)&hin[e01.x * HDIM + 2 * lane]);
        float2 v1 = __ldg((const float2*)&hin[e01.z * HDIM + 2 * lane]);
        float2 v2 = __ldg((const float2*)&hin[e23.x * HDIM + 2 * lane]);
        float2 v3 = __ldg((const float2*)&hin[e23.z * HDIM + 2 * lane]);
        acc0 = fmaf(__int_as_float(e01.y), v0.x, acc0);
        acc1 = fmaf(__int_as_float(e01.y), v0.y, acc1);
        acc0 = fmaf(__int_as_float(e01.w), v1.x, acc0);
        acc1 = fmaf(__int_as_float(e01.w), v1.y, acc1);
        acc0 = fmaf(__int_as_float(e23.y), v2.x, acc0);
        acc1 = fmaf(__int_as_float(e23.y), v2.y, acc1);
        acc0 = fmaf(__int_as_float(e23.w), v3.x, acc0);
        acc1 = fmaf(__int_as_float(e23.w), v3.y, acc1);
    }
    for (; i < e; i++) {
        int2 a0 = g_edges[i];
        float wv = __int_as_float(a0.y);
        float2 v = __ldg((const float2*)&hin[a0.x * HDIM + 2 * lane]);
        acc0 = fmaf(wv, v.x, acc0);
        acc1 = fmaf(wv, v.y, acc1);
    }

    float2 h0v = *(const float2*)&g_h0[node * HDIM + 2 * lane];
    float o0 = 0.9f * acc0 + 0.1f * h0v.x;
    float o1 = 0.9f * acc1 + 0.1f * h0v.y;

    float gg0 = 0.f, gg1 = 0.f;
#pragma unroll
    for (int m = 0; m < 32; m++) {
        float om0 = __shfl_sync(0xffffffffu, o0, m);
        float om1 = __shfl_sync(0xffffffffu, o1, m);
        float2 w0 = *(const float2*)&Wc[2 * m][2 * lane];
        float2 w1 = *(const float2*)&Wc[2 * m + 1][2 * lane];
        gg0 = fmaf(om0, w0.x, gg0);
        gg1 = fmaf(om0, w0.y, gg1);
        gg0 = fmaf(om1, w1.x, gg0);
        gg1 = fmaf(om1, w1.y, gg1);
    }
    float2 r;
    r.x = fmaxf(one_minus_beta * o0 + beta * gg0, 0.f);
    r.y = fmaxf(one_minus_beta * o1 + beta * gg1, 0.f);
    *(float2*)&hout[node * HDIM + 2 * lane] = r;
}

// ---------------- final v3: A-in-registers + shfl, warp = kg x 160 nodes ----------------
// FM=160, 512 threads (16 warps = 2 chunk-parity halves x 8 k-groups), grid 125 = one wave.
// Lane owns 4 packed nodes (4l..4l+3) + 1 scalar node (128+l); 5 k per warp.
// A held in registers (lane <-> pair-in-chunk), broadcast via __shfl -> near-zero
// crossbar traffic for A; P read as unique-data LDS.128 + LDS.32.
#define FM 160
#define FTHR 512
#define KC 32
#define NCHUNK_TOT 65
#define ATS 41                               // padded At row (conflict-free: 41%32=9 odd)
#define OFF_PT  0                            // 2 x [KC][160] = 10240
#define OFF_AT  (OFF_PT + 2 * KC * FM)       // 2 x [KC][41]  = 2624
#define OFF_H   (OFF_AT + 2 * KC * ATS)      // [160][65]     = 10400
#define OFF_N2  (OFF_H + FM * 65)            // 160
#define FK_SMEM_FLOATS (OFF_N2 + FM)         // 23424 floats = 93696 B
#define FK_SMEM_BYTES  (FK_SMEM_FLOATS * 4)
// zs overlays after main loop: zs0 at OFF_PT (6400 <= 10240), zs1 at OFF_H (6400 <= 10400)

__global__ void final_kernel(const float* __restrict__ hin, const float* __restrict__ b1,
                             float* __restrict__ out) {
    extern __shared__ float smem[];
    float* hs  = smem + OFF_H;
    float* n2s = smem + OFF_N2;

    int tid = threadIdx.x;
    int w = tid >> 5;
    int lane = tid & 31;
    int half = w >> 3;        // chunk parity
    int kg = w & 7;           // k-group: ks kg*5..kg*5+4
    int t = tid & 255;        // thread index within half
    float* Pt = smem + OFF_PT + half * (KC * FM);
    float* At = smem + OFF_AT + half * (KC * ATS);
    int n0 = blockIdx.x * FM;

    // load h tile [160][64] -> hs stride 65: 2560 float4 / 512 threads
#pragma unroll
    for (int q = 0; q < 5; q++) {
        int idx = tid + FTHR * q;
        int nd = idx >> 4;
        int j4 = idx & 15;
        int gn = n0 + nd;
        float4 v = make_float4(0.f, 0.f, 0.f, 0.f);
        if (gn < N_NODES) v = *(const float4*)&hin[gn * HDIM + j4 * 4];
        float* hr = hs + nd * 65 + j4 * 4;
        hr[0] = v.x; hr[1] = v.y; hr[2] = v.z; hr[3] = v.w;
    }
    __syncthreads();

    if (tid < FM) {
        float s = 0.f;
        const float* hr = hs + tid * 65;
#pragma unroll
        for (int j = 0; j < 64; j++) s = fmaf(hr[j], hr[j], s);
        n2s[tid] = s;
    }

    ull_t acc0[5], acc1[5];
    float acc2[5];
#pragma unroll
    for (int c = 0; c < 5; c++) { acc0[c] = 0ull; acc1[c] = 0ull; acc2[c] = 0.f; }

    for (int ci = 0; ci < 33; ci++) {
        int chunk = ci * 2 + half;
        bool active = (chunk < NCHUNK_TOT);
        int pc = chunk * KC;
        __syncthreads();
        if (active) {
            // stage compact A chunk: 32x40 floats -> At[kk][41] (padded, conflict-free)
            const float* src = &g_A2[pc * C_OUT];
#pragma unroll
            for (int q = 0; q < 5; q++) {
                int v = t + 256 * q;            // 0..1279
                int kkv = v / C_OUT;
                int kv = v - kkv * C_OUT;
                At[kkv * ATS + kv] = src[v];
            }
            // build P chunk: 32x160 = 5120 / 256 = 20 per thread
#pragma unroll
            for (int q = 0; q < KC * FM / 256; q++) {
                int tt = t + 256 * q;
                int pl = tt / FM;
                int nd = tt - pl * FM;
                int p = pc + pl;
                int i = __ldg(&g_pi[p]);
                int j = __ldg(&g_pj[p]);
                Pt[pl * FM + nd] = hs[nd * 65 + i] * hs[nd * 65 + j];
            }
        }
        __syncthreads();
        if (active) {
            // A for this chunk into registers: lane <-> pair index
            float Af0 = At[lane * ATS + kg * 5 + 0];
            float Af1 = At[lane * ATS + kg * 5 + 1];
            float Af2 = At[lane * ATS + kg * 5 + 2];
            float Af3 = At[lane * ATS + kg * 5 + 3];
            float Af4 = At[lane * ATS + kg * 5 + 4];
#pragma unroll 4
            for (int kk = 0; kk < KC; kk++) {
                double2 pd = *(const double2*)&Pt[kk * FM + 4 * lane];
                float p4 = Pt[kk * FM + 128 + lane];
                ull_t p01 = __double_as_longlong(pd.x);
                ull_t p23 = __double_as_longlong(pd.y);
                float a0 = __shfl_sync(0xffffffffu, Af0, kk);
                float a1 = __shfl_sync(0xffffffffu, Af1, kk);
                float a2 = __shfl_sync(0xffffffffu, Af2, kk);
                float a3 = __shfl_sync(0xffffffffu, Af3, kk);
                float a4 = __shfl_sync(0xffffffffu, Af4, kk);
                ull_t ap0 = pack2(a0, a0);
                ull_t ap1 = pack2(a1, a1);
                ull_t ap2 = pack2(a2, a2);
                ull_t ap3 = pack2(a3, a3);
                ull_t ap4 = pack2(a4, a4);
                FMA_F32X2(acc0[0], p01, ap0, acc0[0]);
                FMA_F32X2(acc1[0], p23, ap0, acc1[0]);
                acc2[0] = fmaf(p4, a0, acc2[0]);
                FMA_F32X2(acc0[1], p01, ap1, acc0[1]);
                FMA_F32X2(acc1[1], p23, ap1, acc1[1]);
                acc2[1] = fmaf(p4, a1, acc2[1]);
                FMA_F32X2(acc0[2], p01, ap2, acc0[2]);
                FMA_F32X2(acc1[2], p23, ap2, acc1[2]);
                acc2[2] = fmaf(p4, a2, acc2[2]);
                FMA_F32X2(acc0[3], p01, ap3, acc0[3]);
                FMA_F32X2(acc1[3], p23, ap3, acc1[3]);
                acc2[3] = fmaf(p4, a3, acc2[3]);
                FMA_F32X2(acc0[4], p01, ap4, acc0[4]);
                FMA_F32X2(acc1[4], p23, ap4, acc1[4]);
                acc2[4] = fmaf(p4, a4, acc2[4]);
            }
        }
    }
    __syncthreads();   // Pt/At/hs dead; zs overlays safe

    // partial z per half: zs0 at OFF_PT, zs1 at OFF_H
    float* zsh = smem + (half == 0 ? OFF_PT : OFF_H);
#pragma unroll
    for (int c = 0; c < 5; c++) {
        int k = kg * 5 + c;
        zsh[(4 * lane + 0) * C_OUT + k] = __uint_as_float((unsigned)(acc0[c] & 0xffffffffull));
        zsh[(4 * lane + 1) * C_OUT + k] = __uint_as_float((unsigned)(acc0[c] >> 32));
        zsh[(4 * lane + 2) * C_OUT + k] = __uint_as_float((unsigned)(acc1[c] & 0xffffffffull));
        zsh[(4 * lane + 3) * C_OUT + k] = __uint_as_float((unsigned)(acc1[c] >> 32));
        zsh[(128 + lane) * C_OUT + k]   = acc2[c];
    }
    __syncthreads();

    // per-node hyperbolic epilogue + log_softmax (threads 0..159)
    if (tid < FM) {
        int gn = n0 + tid;
        if (gn < N_NODES) {
            const float* zs0 = smem + OFF_PT;
            const float* zs1 = smem + OFF_H;
            const float MAXN = 1.0f - 4e-3f;
            float n2 = fmaxf(n2s[tid], 1e-15f);   // ||o|| = ||h||^2
            float pn = fminf(n2, MAXN);
            float tt = atanhf(pn);
            float scale = tt / n2;

            float u[C_OUT];
            float un2 = 0.f;
#pragma unroll
            for (int k = 0; k < C_OUT; k++) {
                float z = zs0[tid * C_OUT + k] + zs1[tid * C_OUT + k];
                float v = scale * z + b1[k];
                u[k] = v;
                un2 = fmaf(v, v, un2);
            }
            float un = fmaxf(sqrtf(un2), 1e-15f);
            float th = tanhf(un);
            float gsc = fminf(th, MAXN) / un;

            float m = -INFINITY;
#pragma unroll
            for (int k = 0; k < C_OUT; k++) {
                u[k] *= gsc;
                m = fmaxf(m, u[k]);
            }
            float se = 0.f;
#pragma unroll
            for (int k = 0; k < C_OUT; k++) se += expf(u[k] - m);
            float lse = m + logf(se);
#pragma unroll
            for (int k = 0; k < C_OUT; k++) out[gn * C_OUT + k] = u[k] - lse;
        }
    }
}

// ---------------- launch ----------------
// 1 hist(+pair init), 2 scan(+cnt reset), 3 fused scatter+lin0, 4 layer0 <- profiled
extern "C" void kernel_launch(void* const* d_in, const int* in_sizes, int n_in,
                              void* d_out, int out_size) {
    const float* x      = (const float*)d_in[0];
    const int*   row    = (const int*)d_in[1];
    const int*   col    = (const int*)d_in[2];
    const float* ew     = (const float*)d_in[3];
    const float* lin0_w = (const float*)d_in[4];
    const float* lin0_b = (const float*)d_in[5];
    const float* conv_w = (const float*)d_in[6];
    const float* lin1_w = (const float*)d_in[7];
    const float* lin1_b = (const float*)d_in[8];
    float* out = (float*)d_out;

    float* hA = nullptr;
    float* hB = nullptr;
    cudaGetSymbolAddress((void**)&hA, g_hA);
    cudaGetSymbolAddress((void**)&hB, g_hB);

    cudaFuncSetAttribute(fused_scatter_lin0, cudaFuncAttributeMaxDynamicSharedMemorySize,
                         L0_SMEM_BYTES);
    cudaFuncSetAttribute(final_kernel, cudaFuncAttributeMaxDynamicSharedMemorySize,
                         FK_SMEM_BYTES);

    hist_kernel<<<(E_EDGES + 255) / 256, 256>>>(row);                       // 1
    scan_kernel<<<1, 1024>>>();                                             // 2
    fused_scatter_lin0<<<SC_BLOCKS + L0_BLOCKS, 512, L0_SMEM_BYTES>>>(
        row, col, ew, x, lin0_w, lin0_b);                                   // 3

    const float* hin = hA;
    float* hout = hB;
    {
        float beta = logf(0.5f / 1.0f + 1.0f);
        layer_kernel<<<(N_NODES + 7) / 8, 256>>>(hin, hout, conv_w,
                                                 1.0f - beta, beta);        // 4 <- profiled
        const float* tmp = hin; hin = hout; hout = (float*)tmp;
    }
    apack_kernel<<<(NPAIR * C_OUT + 255) / 256, 256>>>(lin1_w);             // 5

    for (int l = 1; l < L_LAYERS; l++) {
        float beta = logf(0.5f / (float)(l + 1) + 1.0f);
        layer_kernel<<<(N_NODES + 7) / 8, 256>>>(hin, hout, conv_w + l * HDIM * HDIM,
                                                 1.0f - beta, beta);
        const float* tmp = hin; hin = hout; hout = (float*)tmp;
    }

    final_kernel<<<N_NODES / FM, FTHR, FK_SMEM_BYTES>>>(hin, lin1_b, out);
}

// round 15
// speedup vs baseline: 1.5906x; 1.0501x over previous
#include <cuda_runtime.h>
#include <math.h>

#define N_NODES 20000
#define F_IN    512
#define HDIM    64
#define L_LAYERS 8
#define E_EDGES 640000
#define C_OUT   40
#define NPAIR   2080          // 64*65/2 pairs (i<=j)
#define APR     96            // padded A row: 8 kg * 12 floats (10 used, 16B-aligned)

typedef unsigned long long ull_t;

// ---------------- device scratch (no runtime allocation allowed) ----------------
__device__ float g_h0[N_NODES * HDIM];
__device__ float g_hA[N_NODES * HDIM];
__device__ float g_hB[N_NODES * HDIM];
__device__ int   g_cnt[N_NODES];
__device__ int   g_ptr[N_NODES + 1];
__device__ int   g_cursor[N_NODES];
__device__ int2  g_edges[E_EDGES];            // x = col index, y = float bits of weight
__device__ int   g_pi[NPAIR];
__device__ int   g_pj[NPAIR];
__device__ float g_Apack[NPAIR * APR];        // [p][kg][12]: 5 duplicated k-pairs + pad

#define FMA_F32X2(d, a, b, c) \
    asm("fma.rn.f32x2 %0, %1, %2, %3;" : "=l"(d) : "l"(a), "l"(b), "l"(c))

__device__ __forceinline__ ull_t pack2(float lo, float hi) {
    ull_t r;
    asm("mov.b64 %0, {%1, %2};" : "=l"(r) : "f"(lo), "f"(hi));
    return r;
}

// ---------------- hist (+ pair-table init folded in) ----------------
__global__ void hist_kernel(const int* __restrict__ row) {
    int e = blockIdx.x * blockDim.x + threadIdx.x;
    if (e < E_EDGES) atomicAdd(&g_cnt[row[e]], 1);
    if (e < NPAIR) {
        int i = 0, off = 0;
        while (off + (HDIM - i) <= e) { off += HDIM - i; i++; }
        g_pi[e] = i;
        g_pj[e] = i + (e - off);
    }
}

// single-block exclusive scan over 20000 counters -> g_ptr, g_cursor; resets g_cnt
__global__ void scan_kernel() {
    const int T = 1024;
    const int PER = (N_NODES + T - 1) / T;  // 20
    __shared__ int sums[T];
    int t = threadIdx.x;
    int base = t * PER;
    int local[PER];
    int s = 0;
#pragma unroll
    for (int i = 0; i < PER; i++) {
        int idx = base + i;
        int v = (idx < N_NODES) ? g_cnt[idx] : 0;
        if (idx < N_NODES) g_cnt[idx] = 0;
        local[i] = s;
        s += v;
    }
    sums[t] = s;
    __syncthreads();
    for (int off = 1; off < T; off <<= 1) {
        int v = (t >= off) ? sums[t - off] : 0;
        __syncthreads();
        sums[t] += v;
        __syncthreads();
    }
    int offset = (t == 0) ? 0 : sums[t - 1];
#pragma unroll
    for (int i = 0; i < PER; i++) {
        int idx = base + i;
        if (idx < N_NODES) {
            int p = offset + local[i];
            g_ptr[idx] = p;
            g_cursor[idx] = p;
        }
    }
    if (t == T - 1) g_ptr[N_NODES] = sums[T - 1];
}

// ---------------- fused scatter + lin0 (disjoint block ranges) ----------------
#define SC_BLOCKS ((E_EDGES + 511) / 512)      // 1250
#define L0_RT 144
#define L0_BLOCKS ((N_NODES + L0_RT - 1) / L0_RT)  // 139
#define L0_XS 149
#define L0_XSZ (32 * L0_XS)
#define L0_WSZ (32 * 64)
#define L0_SMEM_FLOATS (2 * L0_XSZ + 2 * L0_WSZ)
#define L0_SMEM_BYTES  (L0_SMEM_FLOATS * 4)

__global__ void fused_scatter_lin0(const int* __restrict__ row, const int* __restrict__ col,
                                   const float* __restrict__ ew,
                                   const float* __restrict__ x, const float* __restrict__ w,
                                   const float* __restrict__ b) {
    if (blockIdx.x < SC_BLOCKS) {
        int e = blockIdx.x * 512 + threadIdx.x;
        if (e < E_EDGES) {
            int r = row[e];
            int pos = atomicAdd(&g_cursor[r], 1);
            g_edges[pos] = make_int2(col[e], __float_as_int(ew[e]));
        }
        return;
    }
    extern __shared__ float sm[];
    int tid = threadIdx.x;
    int kh = tid >> 8;
    int t  = tid & 255;
    int tx = t & 15;
    int ty = t >> 4;
    float* Xs = sm + kh * L0_XSZ;
    float* Ws = sm + 2 * L0_XSZ + kh * L0_WSZ;
    int row0 = (blockIdx.x - SC_BLOCKS) * L0_RT;
    int kbase = kh * 256;

    ull_t acc0[9], acc1[9];
#pragma unroll
    for (int m = 0; m < 9; m++) { acc0[m] = 0ull; acc1[m] = 0ull; }

    float4 xv[5];
    float4 wv[2];
    int xr[5], xk4[5];
    bool xok[5];
#pragma unroll
    for (int q = 0; q < 5; q++) {
        int idx = t + 256 * q;
        xok[q] = (idx < L0_RT * 8);
        xr[q] = idx >> 3;
        xk4[q] = idx & 7;
    }
    int wkk[2], wc4[2];
#pragma unroll
    for (int q = 0; q < 2; q++) {
        int idx = t + 256 * q;
        wkk[q] = idx >> 4;
        wc4[q] = idx & 15;
    }

#pragma unroll
    for (int q = 0; q < 5; q++) {
        xv[q] = make_float4(0.f, 0.f, 0.f, 0.f);
        if (xok[q]) {
            int gr = row0 + xr[q];
            if (gr < N_NODES) xv[q] = *(const float4*)&x[gr * F_IN + kbase + xk4[q] * 4];
        }
    }
#pragma unroll
    for (int q = 0; q < 2; q++)
        wv[q] = *(const float4*)&w[(kbase + wkk[q]) * HDIM + wc4[q] * 4];

    for (int c = 0; c < 8; c++) {
        __syncthreads();
#pragma unroll
        for (int q = 0; q < 5; q++) {
            if (xok[q]) {
                int r = xr[q], k4 = xk4[q];
                Xs[(k4 * 4 + 0) * L0_XS + r] = xv[q].x;
                Xs[(k4 * 4 + 1) * L0_XS + r] = xv[q].y;
                Xs[(k4 * 4 + 2) * L0_XS + r] = xv[q].z;
                Xs[(k4 * 4 + 3) * L0_XS + r] = xv[q].w;
            }
        }
#pragma unroll
        for (int q = 0; q < 2; q++)
            *(float4*)&Ws[wkk[q] * 64 + wc4[q] * 4] = wv[q];
        __syncthreads();

        if (c + 1 < 8) {
            int k0 = kbase + (c + 1) * 32;
#pragma unroll
            for (int q = 0; q < 5; q++) {
                if (xok[q]) {
                    int gr = row0 + xr[q];
                    if (gr < N_NODES)
                        xv[q] = *(const float4*)&x[gr * F_IN + k0 + xk4[q] * 4];
                }
            }
#pragma unroll
            for (int q = 0; q < 2; q++)
                wv[q] = *(const float4*)&w[(k0 + wkk[q]) * HDIM + wc4[q] * 4];
        }

#pragma unroll
        for (int kk = 0; kk < 32; kk++) {
            double2 bd = *(const double2*)&Ws[kk * 64 + tx * 4];
            ull_t b01 = __double_as_longlong(bd.x);
            ull_t b23 = __double_as_longlong(bd.y);
#pragma unroll
            for (int m = 0; m < 9; m++) {
                float a = Xs[kk * L0_XS + ty * 9 + m];
                ull_t pa = pack2(a, a);
                FMA_F32X2(acc0[m], pa, b01, acc0[m]);
                FMA_F32X2(acc1[m], pa, b23, acc1[m]);
            }
        }
    }

    __syncthreads();
    float* part = sm;
    if (kh == 1) {
#pragma unroll
        for (int m = 0; m < 9; m++) {
            float4 v;
            v.x = __uint_as_float((unsigned)(acc0[m] & 0xffffffffull));
            v.y = __uint_as_float((unsigned)(acc0[m] >> 32));
            v.z = __uint_as_float((unsigned)(acc1[m] & 0xffffffffull));
            v.w = __uint_as_float((unsigned)(acc1[m] >> 32));
            *(float4*)&part[t * 36 + m * 4] = v;
        }
    }
    __syncthreads();
    if (kh == 0) {
        float4 bv = *(const float4*)&b[tx * 4];
#pragma unroll
        for (int m = 0; m < 9; m++) {
            int gr = row0 + ty * 9 + m;
            if (gr < N_NODES) {
                float4 p = *(const float4*)&part[t * 36 + m * 4];
                float4 r;
                r.x = fmaxf(__uint_as_float((unsigned)(acc0[m] & 0xffffffffull)) + p.x + bv.x, 0.f);
                r.y = fmaxf(__uint_as_float((unsigned)(acc0[m] >> 32)) + p.y + bv.y, 0.f);
                r.z = fmaxf(__uint_as_float((unsigned)(acc1[m] & 0xffffffffull)) + p.z + bv.z, 0.f);
                r.w = fmaxf(__uint_as_float((unsigned)(acc1[m] >> 32)) + p.w + bv.w, 0.f);
                *(float4*)&g_h0[gr * HDIM + tx * 4] = r;
                *(float4*)&g_hA[gr * HDIM + tx * 4] = r;
            }
        }
    }
}

// duplicated-pair A: g_Apack[p][kg*12 + kc*2 (+1)] = W[(i,j),k] + (i!=j ? W[(j,i),k] : 0)
__global__ void apack_kernel(const float* __restrict__ lin1_w) {
    int idx = blockIdx.x * blockDim.x + threadIdx.x;
    if (idx < NPAIR * C_OUT) {
        int p = idx / C_OUT;
        int k = idx % C_OUT;
        int i = g_pi[p], j = g_pj[p];
        float v = lin1_w[(i * HDIM + j) * C_OUT + k];
        if (i != j) v += lin1_w[(j * HDIM + i) * C_OUT + k];
        int kg = k / 5, kc = k % 5;
        float* dst = &g_Apack[p * APR + kg * 12 + kc * 2];
        dst[0] = v;
        dst[1] = v;
    }
}

// ---------------- fused GCN2 layer (R8/R12/R14 measured-best) ----------------
__global__ void layer_kernel(const float* __restrict__ hin, float* __restrict__ hout,
                             const float* __restrict__ convw, float one_minus_beta, float beta) {
    __shared__ float Wc[64][64];
    int tid = threadIdx.x;
#pragma unroll
    for (int q = 0; q < 4; q++) {
        int idx = tid + 256 * q;
        *(float4*)&Wc[0][idx * 4] = *(const float4*)&convw[idx * 4];
    }
    __syncthreads();

    int warp = tid >> 5, lane = tid & 31;
    int node = blockIdx.x * 8 + warp;
    if (node >= N_NODES) return;

    int s = g_ptr[node];
    int e = g_ptr[node + 1];
    float acc0 = 0.f, acc1 = 0.f;
    int i = s;
    if ((i & 1) && i < e) {
        int2 a0 = g_edges[i];
        float wv = __int_as_float(a0.y);
        float2 v = __ldg((const float2*)&hin[a0.x * HDIM + 2 * lane]);
        acc0 = fmaf(wv, v.x, acc0);
        acc1 = fmaf(wv, v.y, acc1);
        i++;
    }
    for (; i + 8 <= e; i += 8) {
        int4 e01 = *(const int4*)&g_edges[i];
        int4 e23 = *(const int4*)&g_edges[i + 2];
        int4 e45 = *(const int4*)&g_edges[i + 4];
        int4 e67 = *(const int4*)&g_edges[i + 6];
        float2 v0 = __ldg((const float2*)&hin[e01.x * HDIM + 2 * lane]);
        float2 v1 = __ldg((const float2*)&hin[e01.z * HDIM + 2 * lane]);
        float2 v2 = __ldg((const float2*)&hin[e23.x * HDIM + 2 * lane]);
        float2 v3 = __ldg((const float2*)&hin[e23.z * HDIM + 2 * lane]);
        float2 v4 = __ldg((const float2*)&hin[e45.x * HDIM + 2 * lane]);
        float2 v5 = __ldg((const float2*)&hin[e45.z * HDIM + 2 * lane]);
        float2 v6 = __ldg((const float2*)&hin[e67.x * HDIM + 2 * lane]);
        float2 v7 = __ldg((const float2*)&hin[e67.z * HDIM + 2 * lane]);
        acc0 = fmaf(__int_as_float(e01.y), v0.x, acc0);
        acc1 = fmaf(__int_as_float(e01.y), v0.y, acc1);
        acc0 = fmaf(__int_as_float(e01.w), v1.x, acc0);
        acc1 = fmaf(__int_as_float(e01.w), v1.y, acc1);
        acc0 = fmaf(__int_as_float(e23.y), v2.x, acc0);
        acc1 = fmaf(__int_as_float(e23.y), v2.y, acc1);
        acc0 = fmaf(__int_as_float(e23.w), v3.x, acc0);
        acc1 = fmaf(__int_as_float(e23.w), v3.y, acc1);
        acc0 = fmaf(__int_as_float(e45.y), v4.x, acc0);
        acc1 = fmaf(__int_as_float(e45.y), v4.y, acc1);
        acc0 = fmaf(__int_as_float(e45.w), v5.x, acc0);
        acc1 = fmaf(__int_as_float(e45.w), v5.y, acc1);
        acc0 = fmaf(__int_as_float(e67.y), v6.x, acc0);
        acc1 = fmaf(__int_as_float(e67.y), v6.y, acc1);
        acc0 = fmaf(__int_as_float(e67.w), v7.x, acc0);
        acc1 = fmaf(__int_as_float(e67.w), v7.y, acc1);
    }
    for (; i + 4 <= e; i += 4) {
        int4 e01 = *(const int4*)&g_edges[i];
        int4 e23 = *(const int4*)&g_edges[i + 2];
        float2 v0 = __ldg((const float2*)&hin[e01.x * HDIM + 2 * lane]);
        float2 v1 = __ldg((const float2*)&hin[e01.z * HDIM + 2 * lane]);
        float2 v2 = __ldg((const float2*)&hin[e23.x * HDIM + 2 * lane]);
        float2 v3 = __ldg((const float2*)&hin[e23.z * HDIM + 2 * lane]);
        acc0 = fmaf(__int_as_float(e01.y), v0.x, acc0);
        acc1 = fmaf(__int_as_float(e01.y), v0.y, acc1);
        acc0 = fmaf(__int_as_float(e01.w), v1.x, acc0);
        acc1 = fmaf(__int_as_float(e01.w), v1.y, acc1);
        acc0 = fmaf(__int_as_float(e23.y), v2.x, acc0);
        acc1 = fmaf(__int_as_float(e23.y), v2.y, acc1);
        acc0 = fmaf(__int_as_float(e23.w), v3.x, acc0);
        acc1 = fmaf(__int_as_float(e23.w), v3.y, acc1);
    }
    for (; i < e; i++) {
        int2 a0 = g_edges[i];
        float wv = __int_as_float(a0.y);
        float2 v = __ldg((const float2*)&hin[a0.x * HDIM + 2 * lane]);
        acc0 = fmaf(wv, v.x, acc0);
        acc1 = fmaf(wv, v.y, acc1);
    }

    float2 h0v = *(const float2*)&g_h0[node * HDIM + 2 * lane];
    float o0 = 0.9f * acc0 + 0.1f * h0v.x;
    float o1 = 0.9f * acc1 + 0.1f * h0v.y;

    float gg0 = 0.f, gg1 = 0.f;
#pragma unroll
    for (int m = 0; m < 32; m++) {
        float om0 = __shfl_sync(0xffffffffu, o0, m);
        float om1 = __shfl_sync(0xffffffffu, o1, m);
        float2 w0 = *(const float2*)&Wc[2 * m][2 * lane];
        float2 w1 = *(const float2*)&Wc[2 * m + 1][2 * lane];
        gg0 = fmaf(om0, w0.x, gg0);
        gg1 = fmaf(om0, w0.y, gg1);
        gg0 = fmaf(om1, w1.x, gg0);
        gg1 = fmaf(om1, w1.y, gg1);
    }
    float2 r;
    r.x = fmaxf(one_minus_beta * o0 + beta * gg0, 0.f);
    r.y = fmaxf(one_minus_beta * o1 + beta * gg1, 0.f);
    *(float2*)&hout[node * HDIM + 2 * lane] = r;
}

// ---------------- final v4: v3 tiling + broadcast-LDS A (no shfl, no pack) ----------------
// FM=160, 512 threads (16 warps = 2 chunk-parity halves x 8 k-groups), grid 125 = one wave.
// Warp = ONE k-group -> every lane reads the SAME A address: LDS broadcast, 1 wavefront.
// Lane owns 4 packed nodes (4l..4l+3) + 1 scalar node (128+l).
// Per kk: LDS.128(P) + LDS.32(p4) + 3 broadcast LDS(A) + 15 FMA = 20 issue slots / 800 MACs.
#define FM 160
#define FTHR 512
#define KC 32
#define NCHUNK_TOT 65
#define OFF_PT  0                            // 2 x [KC][160] = 10240
#define OFF_AT  (OFF_PT + 2 * KC * FM)       // 2 x [KC][APR] = 6144
#define OFF_H   (OFF_AT + 2 * KC * APR)      // [160][65]     = 10400
#define OFF_N2  (OFF_H + FM * 65)            // 160
#define FK_SMEM_FLOATS (OFF_N2 + FM)         // 26944 floats = 107776 B
#define FK_SMEM_BYTES  (FK_SMEM_FLOATS * 4)
// zs overlays after main loop: zs0 at OFF_PT (6400 <= 10240), zs1 at OFF_H (6400 <= 10400)

__global__ void final_kernel(const float* __restrict__ hin, const float* __restrict__ b1,
                             float* __restrict__ out) {
    extern __shared__ float smem[];
    float* hs  = smem + OFF_H;
    float* n2s = smem + OFF_N2;

    int tid = threadIdx.x;
    int w = tid >> 5;
    int lane = tid & 31;
    int half = w >> 3;        // chunk parity
    int kg = w & 7;           // k-group: ks kg*5..kg*5+4
    int t = tid & 255;        // thread index within half
    float* Pt = smem + OFF_PT + half * (KC * FM);
    float* At = smem + OFF_AT + half * (KC * APR);
    int n0 = blockIdx.x * FM;

    // load h tile [160][64] -> hs stride 65: 2560 float4 / 512 threads
#pragma unroll
    for (int q = 0; q < 5; q++) {
        int idx = tid + FTHR * q;
        int nd = idx >> 4;
        int j4 = idx & 15;
        int gn = n0 + nd;
        float4 v = make_float4(0.f, 0.f, 0.f, 0.f);
        if (gn < N_NODES) v = *(const float4*)&hin[gn * HDIM + j4 * 4];
        float* hr = hs + nd * 65 + j4 * 4;
        hr[0] = v.x; hr[1] = v.y; hr[2] = v.z; hr[3] = v.w;
    }
    __syncthreads();

    if (tid < FM) {
        float s = 0.f;
        const float* hr = hs + tid * 65;
#pragma unroll
        for (int j = 0; j < 64; j++) s = fmaf(hr[j], hr[j], s);
        n2s[tid] = s;
    }

    ull_t acc0[5], acc1[5];
    float acc2[5];
#pragma unroll
    for (int c = 0; c < 5; c++) { acc0[c] = 0ull; acc1[c] = 0ull; acc2[c] = 0.f; }

    for (int ci = 0; ci < 33; ci++) {
        int chunk = ci * 2 + half;
        bool active = (chunk < NCHUNK_TOT);
        int pc = chunk * KC;
        __syncthreads();
        if (active) {
            // stage duplicated A chunk: 32*96 floats = 768 float4 / 256 thr = 3 each
            const float4* src = (const float4*)&g_Apack[pc * APR];
#pragma unroll
            for (int q = 0; q < KC * APR / 4 / 256; q++) {
                int v = t + 256 * q;
                *(float4*)&At[v * 4] = src[v];
            }
            // build P chunk: 32x160 = 5120 / 256 = 20 per thread
#pragma unroll
            for (int q = 0; q < KC * FM / 256; q++) {
                int tt = t + 256 * q;
                int pl = tt / FM;
                int nd = tt - pl * FM;
                int p = pc + pl;
                int i = __ldg(&g_pi[p]);
                int j = __ldg(&g_pj[p]);
                Pt[pl * FM + nd] = hs[nd * 65 + i] * hs[nd * 65 + j];
            }
        }
        __syncthreads();
        if (active) {
#pragma unroll 4
            for (int kk = 0; kk < KC; kk++) {
                double2 pd = *(const double2*)&Pt[kk * FM + 4 * lane];
                float p4 = Pt[kk * FM + 128 + lane];
                ull_t p01 = __double_as_longlong(pd.x);
                ull_t p23 = __double_as_longlong(pd.y);
                // warp-uniform A address -> broadcast LDS (1 wavefront each)
                const float* arow = At + kk * APR + kg * 12;
                double2 a01 = *(const double2*)arow;
                double2 a23 = *(const double2*)(arow + 4);
                ull_t a4 = *(const ull_t*)(arow + 8);
                ull_t a0 = __double_as_longlong(a01.x);
                ull_t a1 = __double_as_longlong(a01.y);
                ull_t a2 = __double_as_longlong(a23.x);
                ull_t a3 = __double_as_longlong(a23.y);
                float a0s = __uint_as_float((unsigned)(a0 & 0xffffffffull));
                float a1s = __uint_as_float((unsigned)(a1 & 0xffffffffull));
                float a2s = __uint_as_float((unsigned)(a2 & 0xffffffffull));
                float a3s = __uint_as_float((unsigned)(a3 & 0xffffffffull));
                float a4s = __uint_as_float((unsigned)(a4 & 0xffffffffull));
                FMA_F32X2(acc0[0], p01, a0, acc0[0]);
                FMA_F32X2(acc1[0], p23, a0, acc1[0]);
                acc2[0] = fmaf(p4, a0s, acc2[0]);
                FMA_F32X2(acc0[1], p01, a1, acc0[1]);
                FMA_F32X2(acc1[1], p23, a1, acc1[1]);
                acc2[1] = fmaf(p4, a1s, acc2[1]);
                FMA_F32X2(acc0[2], p01, a2, acc0[2]);
                FMA_F32X2(acc1[2], p23, a2, acc1[2]);
                acc2[2] = fmaf(p4, a2s, acc2[2]);
                FMA_F32X2(acc0[3], p01, a3, acc0[3]);
                FMA_F32X2(acc1[3], p23, a3, acc1[3]);
                acc2[3] = fmaf(p4, a3s, acc2[3]);
                FMA_F32X2(acc0[4], p01, a4, acc0[4]);
                FMA_F32X2(acc1[4], p23, a4, acc1[4]);
                acc2[4] = fmaf(p4, a4s, acc2[4]);
            }
        }
    }
    __syncthreads();   // Pt/At/hs dead; zs overlays safe

    // partial z per half: zs0 at OFF_PT, zs1 at OFF_H
    float* zsh = smem + (half == 0 ? OFF_PT : OFF_H);
#pragma unroll
    for (int c = 0; c < 5; c++) {
        int k = kg * 5 + c;
        zsh[(4 * lane + 0) * C_OUT + k] = __uint_as_float((unsigned)(acc0[c] & 0xffffffffull));
        zsh[(4 * lane + 1) * C_OUT + k] = __uint_as_float((unsigned)(acc0[c] >> 32));
        zsh[(4 * lane + 2) * C_OUT + k] = __uint_as_float((unsigned)(acc1[c] & 0xffffffffull));
        zsh[(4 * lane + 3) * C_OUT + k] = __uint_as_float((unsigned)(acc1[c] >> 32));
        zsh[(128 + lane) * C_OUT + k]   = acc2[c];
    }
    __syncthreads();

    // per-node hyperbolic epilogue + log_softmax (threads 0..159)
    if (tid < FM) {
        int gn = n0 + tid;
        if (gn < N_NODES) {
            const float* zs0 = smem + OFF_PT;
            const float* zs1 = smem + OFF_H;
            const float MAXN = 1.0f - 4e-3f;
            float n2 = fmaxf(n2s[tid], 1e-15f);   // ||o|| = ||h||^2
            float pn = fminf(n2, MAXN);
            float tt = atanhf(pn);
            float scale = tt / n2;

            float u[C_OUT];
            float un2 = 0.f;
#pragma unroll
            for (int k = 0; k < C_OUT; k++) {
                float z = zs0[tid * C_OUT + k] + zs1[tid * C_OUT + k];
                float v = scale * z + b1[k];
                u[k] = v;
                un2 = fmaf(v, v, un2);
            }
            float un = fmaxf(sqrtf(un2), 1e-15f);
            float th = tanhf(un);
            float gsc = fminf(th, MAXN) / un;

            float m = -INFINITY;
#pragma unroll
            for (int k = 0; k < C_OUT; k++) {
                u[k] *= gsc;
                m = fmaxf(m, u[k]);
            }
            float se = 0.f;
#pragma unroll
            for (int k = 0; k < C_OUT; k++) se += expf(u[k] - m);
            float lse = m + logf(se);
#pragma unroll
            for (int k = 0; k < C_OUT; k++) out[gn * C_OUT + k] = u[k] - lse;
        }
    }
}

// ---------------- launch ----------------
// 1 hist(+pair init), 2 scan(+cnt reset), 3 fused scatter+lin0, 4 layer0 <- profiled
extern "C" void kernel_launch(void* const* d_in, const int* in_sizes, int n_in,
                              void* d_out, int out_size) {
    const float* x      = (const float*)d_in[0];
    const int*   row    = (const int*)d_in[1];
    const int*   col    = (const int*)d_in[2];
    const float* ew     = (const float*)d_in[3];
    const float* lin0_w = (const float*)d_in[4];
    const float* lin0_b = (const float*)d_in[5];
    const float* conv_w = (const float*)d_in[6];
    const float* lin1_w = (const float*)d_in[7];
    const float* lin1_b = (const float*)d_in[8];
    float* out = (float*)d_out;

    float* hA = nullptr;
    float* hB = nullptr;
    cudaGetSymbolAddress((void**)&hA, g_hA);
    cudaGetSymbolAddress((void**)&hB, g_hB);

    cudaFuncSetAttribute(fused_scatter_lin0, cudaFuncAttributeMaxDynamicSharedMemorySize,
                         L0_SMEM_BYTES);
    cudaFuncSetAttribute(final_kernel, cudaFuncAttributeMaxDynamicSharedMemorySize,
                         FK_SMEM_BYTES);

    hist_kernel<<<(E_EDGES + 255) / 256, 256>>>(row);                       // 1
    scan_kernel<<<1, 1024>>>();                                             // 2
    fused_scatter_lin0<<<SC_BLOCKS + L0_BLOCKS, 512, L0_SMEM_BYTES>>>(
        row, col, ew, x, lin0_w, lin0_b);                                   // 3

    const float* hin = hA;
    float* hout = hB;
    {
        float beta = logf(0.5f / 1.0f + 1.0f);
        layer_kernel<<<(N_NODES + 7) / 8, 256>>>(hin, hout, conv_w,
                                                 1.0f - beta, beta);        // 4 <- profiled
        const float* tmp = hin; hin = hout; hout = (float*)tmp;
    }
    apack_kernel<<<(NPAIR * C_OUT + 255) / 256, 256>>>(lin1_w);             // 5

    for (int l = 1; l < L_LAYERS; l++) {
        float beta = logf(0.5f / (float)(l + 1) + 1.0f);
        layer_kernel<<<(N_NODES + 7) / 8, 256>>>(hin, hout, conv_w + l * HDIM * HDIM,
                                                 1.0f - beta, beta);
        const float* tmp = hin; hin = hout; hout = (float*)tmp;
    }

    final_kernel<<<N_NODES / FM, FTHR, FK_SMEM_BYTES>>>(hin, lin1_b, out);
}

// round 16
// speedup vs baseline: 1.7625x; 1.1081x over previous
#include <cuda_runtime.h>
#include <math.h>

#define N_NODES 20000
#define F_IN    512
#define HDIM    64
#define L_LAYERS 8
#define E_EDGES 640000
#define C_OUT   40
#define NPAIR   2080          // 64*65/2 pairs (i<=j)
#define APR     96            // padded A row: 8 kg * 12 floats (10 used, 16B-aligned)

typedef unsigned long long ull_t;

// ---------------- device scratch (no runtime allocation allowed) ----------------
__device__ float g_h0[N_NODES * HDIM];
__device__ float g_hA[N_NODES * HDIM];
__device__ float g_hB[N_NODES * HDIM];
__device__ float g_tmp[N_NODES * HDIM];       // spmm output (pre-conv)
__device__ int   g_cnt[N_NODES];
__device__ int   g_ptr[N_NODES + 1];
__device__ int   g_cursor[N_NODES];
__device__ int2  g_edges[E_EDGES];            // x = col index, y = float bits of weight
__device__ int   g_pi[NPAIR];
__device__ int   g_pj[NPAIR];
__device__ float g_Apack[NPAIR * APR];        // [p][kg][12]: 5 duplicated k-pairs + pad

#define FMA_F32X2(d, a, b, c) \
    asm("fma.rn.f32x2 %0, %1, %2, %3;" : "=l"(d) : "l"(a), "l"(b), "l"(c))

__device__ __forceinline__ ull_t pack2(float lo, float hi) {
    ull_t r;
    asm("mov.b64 %0, {%1, %2};" : "=l"(r) : "f"(lo), "f"(hi));
    return r;
}

// ---------------- hist (+ pair-table init folded in) ----------------
__global__ void hist_kernel(const int* __restrict__ row) {
    int e = blockIdx.x * blockDim.x + threadIdx.x;
    if (e < E_EDGES) atomicAdd(&g_cnt[row[e]], 1);
    if (e < NPAIR) {
        int i = 0, off = 0;
        while (off + (HDIM - i) <= e) { off += HDIM - i; i++; }
        g_pi[e] = i;
        g_pj[e] = i + (e - off);
    }
}

// single-block exclusive scan over 20000 counters -> g_ptr, g_cursor; resets g_cnt
__global__ void scan_kernel() {
    const int T = 1024;
    const int PER = (N_NODES + T - 1) / T;  // 20
    __shared__ int sums[T];
    int t = threadIdx.x;
    int base = t * PER;
    int local[PER];
    int s = 0;
#pragma unroll
    for (int i = 0; i < PER; i++) {
        int idx = base + i;
        int v = (idx < N_NODES) ? g_cnt[idx] : 0;
        if (idx < N_NODES) g_cnt[idx] = 0;
        local[i] = s;
        s += v;
    }
    sums[t] = s;
    __syncthreads();
    for (int off = 1; off < T; off <<= 1) {
        int v = (t >= off) ? sums[t - off] : 0;
        __syncthreads();
        sums[t] += v;
        __syncthreads();
    }
    int offset = (t == 0) ? 0 : sums[t - 1];
#pragma unroll
    for (int i = 0; i < PER; i++) {
        int idx = base + i;
        if (idx < N_NODES) {
            int p = offset + local[i];
            g_ptr[idx] = p;
            g_cursor[idx] = p;
        }
    }
    if (t == T - 1) g_ptr[N_NODES] = sums[T - 1];
}

// ---------------- fused scatter + lin0 (disjoint block ranges) ----------------
#define SC_BLOCKS ((E_EDGES + 511) / 512)      // 1250
#define L0_RT 144
#define L0_BLOCKS ((N_NODES + L0_RT - 1) / L0_RT)  // 139
#define L0_XS 149
#define L0_XSZ (32 * L0_XS)
#define L0_WSZ (32 * 64)
#define L0_SMEM_FLOATS (2 * L0_XSZ + 2 * L0_WSZ)
#define L0_SMEM_BYTES  (L0_SMEM_FLOATS * 4)

__global__ void fused_scatter_lin0(const int* __restrict__ row, const int* __restrict__ col,
                                   const float* __restrict__ ew,
                                   const float* __restrict__ x, const float* __restrict__ w,
                                   const float* __restrict__ b) {
    if (blockIdx.x < SC_BLOCKS) {
        int e = blockIdx.x * 512 + threadIdx.x;
        if (e < E_EDGES) {
            int r = row[e];
            int pos = atomicAdd(&g_cursor[r], 1);
            g_edges[pos] = make_int2(col[e], __float_as_int(ew[e]));
        }
        return;
    }
    extern __shared__ float sm[];
    int tid = threadIdx.x;
    int kh = tid >> 8;
    int t  = tid & 255;
    int tx = t & 15;
    int ty = t >> 4;
    float* Xs = sm + kh * L0_XSZ;
    float* Ws = sm + 2 * L0_XSZ + kh * L0_WSZ;
    int row0 = (blockIdx.x - SC_BLOCKS) * L0_RT;
    int kbase = kh * 256;

    ull_t acc0[9], acc1[9];
#pragma unroll
    for (int m = 0; m < 9; m++) { acc0[m] = 0ull; acc1[m] = 0ull; }

    float4 xv[5];
    float4 wv[2];
    int xr[5], xk4[5];
    bool xok[5];
#pragma unroll
    for (int q = 0; q < 5; q++) {
        int idx = t + 256 * q;
        xok[q] = (idx < L0_RT * 8);
        xr[q] = idx >> 3;
        xk4[q] = idx & 7;
    }
    int wkk[2], wc4[2];
#pragma unroll
    for (int q = 0; q < 2; q++) {
        int idx = t + 256 * q;
        wkk[q] = idx >> 4;
        wc4[q] = idx & 15;
    }

#pragma unroll
    for (int q = 0; q < 5; q++) {
        xv[q] = make_float4(0.f, 0.f, 0.f, 0.f);
        if (xok[q]) {
            int gr = row0 + xr[q];
            if (gr < N_NODES) xv[q] = *(const float4*)&x[gr * F_IN + kbase + xk4[q] * 4];
        }
    }
#pragma unroll
    for (int q = 0; q < 2; q++)
        wv[q] = *(const float4*)&w[(kbase + wkk[q]) * HDIM + wc4[q] * 4];

    for (int c = 0; c < 8; c++) {
        __syncthreads();
#pragma unroll
        for (int q = 0; q < 5; q++) {
            if (xok[q]) {
                int r = xr[q], k4 = xk4[q];
                Xs[(k4 * 4 + 0) * L0_XS + r] = xv[q].x;
                Xs[(k4 * 4 + 1) * L0_XS + r] = xv[q].y;
                Xs[(k4 * 4 + 2) * L0_XS + r] = xv[q].z;
                Xs[(k4 * 4 + 3) * L0_XS + r] = xv[q].w;
            }
        }
#pragma unroll
        for (int q = 0; q < 2; q++)
            *(float4*)&Ws[wkk[q] * 64 + wc4[q] * 4] = wv[q];
        __syncthreads();

        if (c + 1 < 8) {
            int k0 = kbase + (c + 1) * 32;
#pragma unroll
            for (int q = 0; q < 5; q++) {
                if (xok[q]) {
                    int gr = row0 + xr[q];
                    if (gr < N_NODES)
                        xv[q] = *(const float4*)&x[gr * F_IN + k0 + xk4[q] * 4];
                }
            }
#pragma unroll
            for (int q = 0; q < 2; q++)
                wv[q] = *(const float4*)&w[(k0 + wkk[q]) * HDIM + wc4[q] * 4];
        }

#pragma unroll
        for (int kk = 0; kk < 32; kk++) {
            double2 bd = *(const double2*)&Ws[kk * 64 + tx * 4];
            ull_t b01 = __double_as_longlong(bd.x);
            ull_t b23 = __double_as_longlong(bd.y);
#pragma unroll
            for (int m = 0; m < 9; m++) {
                float a = Xs[kk * L0_XS + ty * 9 + m];
                ull_t pa = pack2(a, a);
                FMA_F32X2(acc0[m], pa, b01, acc0[m]);
                FMA_F32X2(acc1[m], pa, b23, acc1[m]);
            }
        }
    }

    __syncthreads();
    float* part = sm;
    if (kh == 1) {
#pragma unroll
        for (int m = 0; m < 9; m++) {
            float4 v;
            v.x = __uint_as_float((unsigned)(acc0[m] & 0xffffffffull));
            v.y = __uint_as_float((unsigned)(acc0[m] >> 32));
            v.z = __uint_as_float((unsigned)(acc1[m] & 0xffffffffull));
            v.w = __uint_as_float((unsigned)(acc1[m] >> 32));
            *(float4*)&part[t * 36 + m * 4] = v;
        }
    }
    __syncthreads();
    if (kh == 0) {
        float4 bv = *(const float4*)&b[tx * 4];
#pragma unroll
        for (int m = 0; m < 9; m++) {
            int gr = row0 + ty * 9 + m;
            if (gr < N_NODES) {
                float4 p = *(const float4*)&part[t * 36 + m * 4];
                float4 r;
                r.x = fmaxf(__uint_as_float((unsigned)(acc0[m] & 0xffffffffull)) + p.x + bv.x, 0.f);
                r.y = fmaxf(__uint_as_float((unsigned)(acc0[m] >> 32)) + p.y + bv.y, 0.f);
                r.z = fmaxf(__uint_as_float((unsigned)(acc1[m] & 0xffffffffull)) + p.z + bv.z, 0.f);
                r.w = fmaxf(__uint_as_float((unsigned)(acc1[m] >> 32)) + p.w + bv.w, 0.f);
                *(float4*)&g_h0[gr * HDIM + tx * 4] = r;
                *(float4*)&g_hA[gr * HDIM + tx * 4] = r;
            }
        }
    }
}

// duplicated-pair A: g_Apack[p][kg*12 + kc*2 (+1)] = W[(i,j),k] + (i!=j ? W[(j,i),k] : 0)
__global__ void apack_kernel(const float* __restrict__ lin1_w) {
    int idx = blockIdx.x * blockDim.x + threadIdx.x;
    if (idx < NPAIR * C_OUT) {
        int p = idx / C_OUT;
        int k = idx % C_OUT;
        int i = g_pi[p], j = g_pj[p];
        float v = lin1_w[(i * HDIM + j) * C_OUT + k];
        if (i != j) v += lin1_w[(j * HDIM + i) * C_OUT + k];
        int kg = k / 5, kc = k % 5;
        float* dst = &g_Apack[p * APR + kg * 12 + kc * 2];
        dst[0] = v;
        dst[1] = v;
    }
}

// ---------------- layer part (a): spmm + initial residual only ----------------
// one warp per node; lane owns columns 2*lane, 2*lane+1 (float2 gathers, 8-edge unroll)
__global__ void spmm_kernel(const float* __restrict__ hin, float* __restrict__ outb) {
    int tid = threadIdx.x;
    int warp = tid >> 5, lane = tid & 31;
    int node = blockIdx.x * 8 + warp;
    if (node >= N_NODES) return;

    int s = g_ptr[node];
    int e = g_ptr[node + 1];
    float acc0 = 0.f, acc1 = 0.f;
    int i = s;
    if ((i & 1) && i < e) {
        int2 a0 = g_edges[i];
        float wv = __int_as_float(a0.y);
        float2 v = __ldg((const float2*)&hin[a0.x * HDIM + 2 * lane]);
        acc0 = fmaf(wv, v.x, acc0);
        acc1 = fmaf(wv, v.y, acc1);
        i++;
    }
    for (; i + 8 <= e; i += 8) {
        int4 e01 = *(const int4*)&g_edges[i];
        int4 e23 = *(const int4*)&g_edges[i + 2];
        int4 e45 = *(const int4*)&g_edges[i + 4];
        int4 e67 = *(const int4*)&g_edges[i + 6];
        float2 v0 = __ldg((const float2*)&hin[e01.x * HDIM + 2 * lane]);
        float2 v1 = __ldg((const float2*)&hin[e01.z * HDIM + 2 * lane]);
        float2 v2 = __ldg((const float2*)&hin[e23.x * HDIM + 2 * lane]);
        float2 v3 = __ldg((const float2*)&hin[e23.z * HDIM + 2 * lane]);
        float2 v4 = __ldg((const float2*)&hin[e45.x * HDIM + 2 * lane]);
        float2 v5 = __ldg((const float2*)&hin[e45.z * HDIM + 2 * lane]);
        float2 v6 = __ldg((const float2*)&hin[e67.x * HDIM + 2 * lane]);
        float2 v7 = __ldg((const float2*)&hin[e67.z * HDIM + 2 * lane]);
        acc0 = fmaf(__int_as_float(e01.y), v0.x, acc0);
        acc1 = fmaf(__int_as_float(e01.y), v0.y, acc1);
        acc0 = fmaf(__int_as_float(e01.w), v1.x, acc0);
        acc1 = fmaf(__int_as_float(e01.w), v1.y, acc1);
        acc0 = fmaf(__int_as_float(e23.y), v2.x, acc0);
        acc1 = fmaf(__int_as_float(e23.y), v2.y, acc1);
        acc0 = fmaf(__int_as_float(e23.w), v3.x, acc0);
        acc1 = fmaf(__int_as_float(e23.w), v3.y, acc1);
        acc0 = fmaf(__int_as_float(e45.y), v4.x, acc0);
        acc1 = fmaf(__int_as_float(e45.y), v4.y, acc1);
        acc0 = fmaf(__int_as_float(e45.w), v5.x, acc0);
        acc1 = fmaf(__int_as_float(e45.w), v5.y, acc1);
        acc0 = fmaf(__int_as_float(e67.y), v6.x, acc0);
        acc1 = fmaf(__int_as_float(e67.y), v6.y, acc1);
        acc0 = fmaf(__int_as_float(e67.w), v7.x, acc0);
        acc1 = fmaf(__int_as_float(e67.w), v7.y, acc1);
    }
    for (; i + 4 <= e; i += 4) {
        int4 e01 = *(const int4*)&g_edges[i];
        int4 e23 = *(const int4*)&g_edges[i + 2];
        float2 v0 = __ldg((const float2*)&hin[e01.x * HDIM + 2 * lane]);
        float2 v1 = __ldg((const float2*)&hin[e01.z * HDIM + 2 * lane]);
        float2 v2 = __ldg((const float2*)&hin[e23.x * HDIM + 2 * lane]);
        float2 v3 = __ldg((const float2*)&hin[e23.z * HDIM + 2 * lane]);
        acc0 = fmaf(__int_as_float(e01.y), v0.x, acc0);
        acc1 = fmaf(__int_as_float(e01.y), v0.y, acc1);
        acc0 = fmaf(__int_as_float(e01.w), v1.x, acc0);
        acc1 = fmaf(__int_as_float(e01.w), v1.y, acc1);
        acc0 = fmaf(__int_as_float(e23.y), v2.x, acc0);
        acc1 = fmaf(__int_as_float(e23.y), v2.y, acc1);
        acc0 = fmaf(__int_as_float(e23.w), v3.x, acc0);
        acc1 = fmaf(__int_as_float(e23.w), v3.y, acc1);
    }
    for (; i < e; i++) {
        int2 a0 = g_edges[i];
        float wv = __int_as_float(a0.y);
        float2 v = __ldg((const float2*)&hin[a0.x * HDIM + 2 * lane]);
        acc0 = fmaf(wv, v.x, acc0);
        acc1 = fmaf(wv, v.y, acc1);
    }

    float2 h0v = *(const float2*)&g_h0[node * HDIM + 2 * lane];
    float2 o;
    o.x = 0.9f * acc0 + 0.1f * h0v.x;
    o.y = 0.9f * acc1 + 0.1f * h0v.y;
    *(float2*)&outb[node * HDIM + 2 * lane] = o;
}

// ---------------- layer part (b): h = relu((1-beta)*out + beta*(out @ W)) ----------------
// lin0-style one-wave GEMM: 512 threads, 2 K-halves of 32, 144 rows/block, grid 139.
__global__ void mixmm_kernel(const float* __restrict__ outb, const float* __restrict__ w,
                             float* __restrict__ hout, float one_minus_beta, float beta) {
    extern __shared__ float sm[];
    int tid = threadIdx.x;
    int kh = tid >> 8;
    int t  = tid & 255;
    int tx = t & 15;
    int ty = t >> 4;
    float* Xs = sm + kh * L0_XSZ;
    float* Ws = sm + 2 * L0_XSZ + kh * L0_WSZ;
    int row0 = blockIdx.x * L0_RT;
    int kbase = kh * 32;

    ull_t acc0[9], acc1[9];
#pragma unroll
    for (int m = 0; m < 9; m++) { acc0[m] = 0ull; acc1[m] = 0ull; }

    // stage out tile (144 rows x 32 k of this half), transposed
#pragma unroll
    for (int q = 0; q < 5; q++) {
        int idx = t + 256 * q;
        if (idx < L0_RT * 8) {
            int r = idx >> 3;
            int k4 = idx & 7;
            int gr = row0 + r;
            float4 v = make_float4(0.f, 0.f, 0.f, 0.f);
            if (gr < N_NODES) v = *(const float4*)&outb[gr * HDIM + kbase + k4 * 4];
            Xs[(k4 * 4 + 0) * L0_XS + r] = v.x;
            Xs[(k4 * 4 + 1) * L0_XS + r] = v.y;
            Xs[(k4 * 4 + 2) * L0_XS + r] = v.z;
            Xs[(k4 * 4 + 3) * L0_XS + r] = v.w;
        }
    }
    // stage W half (32 x 64)
#pragma unroll
    for (int q = 0; q < 2; q++) {
        int idx = t + 256 * q;
        int kk = idx >> 4;
        int c4 = idx & 15;
        *(float4*)&Ws[kk * 64 + c4 * 4] = *(const float4*)&w[(kbase + kk) * HDIM + c4 * 4];
    }
    __syncthreads();

#pragma unroll
    for (int kk = 0; kk < 32; kk++) {
        double2 bd = *(const double2*)&Ws[kk * 64 + tx * 4];
        ull_t b01 = __double_as_longlong(bd.x);
        ull_t b23 = __double_as_longlong(bd.y);
#pragma unroll
        for (int m = 0; m < 9; m++) {
            float a = Xs[kk * L0_XS + ty * 9 + m];
            ull_t pa = pack2(a, a);
            FMA_F32X2(acc0[m], pa, b01, acc0[m]);
            FMA_F32X2(acc1[m], pa, b23, acc1[m]);
        }
    }

    __syncthreads();
    float* part = sm;
    if (kh == 1) {
#pragma unroll
        for (int m = 0; m < 9; m++) {
            float4 v;
            v.x = __uint_as_float((unsigned)(acc0[m] & 0xffffffffull));
            v.y = __uint_as_float((unsigned)(acc0[m] >> 32));
            v.z = __uint_as_float((unsigned)(acc1[m] & 0xffffffffull));
            v.w = __uint_as_float((unsigned)(acc1[m] >> 32));
            *(float4*)&part[t * 36 + m * 4] = v;
        }
    }
    __syncthreads();
    if (kh == 0) {
#pragma unroll
        for (int m = 0; m < 9; m++) {
            int gr = row0 + ty * 9 + m;
            if (gr < N_NODES) {
                float4 p = *(const float4*)&part[t * 36 + m * 4];
                float4 ov = *(const float4*)&outb[gr * HDIM + tx * 4];
                float g0 = __uint_as_float((unsigned)(acc0[m] & 0xffffffffull)) + p.x;
                float g1 = __uint_as_float((unsigned)(acc0[m] >> 32)) + p.y;
                float g2 = __uint_as_float((unsigned)(acc1[m] & 0xffffffffull)) + p.z;
                float g3 = __uint_as_float((unsigned)(acc1[m] >> 32)) + p.w;
                float4 r;
                r.x = fmaxf(one_minus_beta * ov.x + beta * g0, 0.f);
                r.y = fmaxf(one_minus_beta * ov.y + beta * g1, 0.f);
                r.z = fmaxf(one_minus_beta * ov.z + beta * g2, 0.f);
                r.w = fmaxf(one_minus_beta * ov.w + beta * g3, 0.f);
                *(float4*)&hout[gr * HDIM + tx * 4] = r;
            }
        }
    }
}

// ---------------- final v4 (R15 measured-best, unchanged) ----------------
#define FM 160
#define FTHR 512
#define KC 32
#define NCHUNK_TOT 65
#define OFF_PT  0
#define OFF_AT  (OFF_PT + 2 * KC * FM)
#define OFF_H   (OFF_AT + 2 * KC * APR)
#define OFF_N2  (OFF_H + FM * 65)
#define FK_SMEM_FLOATS (OFF_N2 + FM)
#define FK_SMEM_BYTES  (FK_SMEM_FLOATS * 4)

__global__ void final_kernel(const float* __restrict__ hin, const float* __restrict__ b1,
                             float* __restrict__ out) {
    extern __shared__ float smem[];
    float* hs  = smem + OFF_H;
    float* n2s = smem + OFF_N2;

    int tid = threadIdx.x;
    int w = tid >> 5;
    int lane = tid & 31;
    int half = w >> 3;
    int kg = w & 7;
    int t = tid & 255;
    float* Pt = smem + OFF_PT + half * (KC * FM);
    float* At = smem + OFF_AT + half * (KC * APR);
    int n0 = blockIdx.x * FM;

#pragma unroll
    for (int q = 0; q < 5; q++) {
        int idx = tid + FTHR * q;
        int nd = idx >> 4;
        int j4 = idx & 15;
        int gn = n0 + nd;
        float4 v = make_float4(0.f, 0.f, 0.f, 0.f);
        if (gn < N_NODES) v = *(const float4*)&hin[gn * HDIM + j4 * 4];
        float* hr = hs + nd * 65 + j4 * 4;
        hr[0] = v.x; hr[1] = v.y; hr[2] = v.z; hr[3] = v.w;
    }
    __syncthreads();

    if (tid < FM) {
        float s = 0.f;
        const float* hr = hs + tid * 65;
#pragma unroll
        for (int j = 0; j < 64; j++) s = fmaf(hr[j], hr[j], s);
        n2s[tid] = s;
    }

    ull_t acc0[5], acc1[5];
    float acc2[5];
#pragma unroll
    for (int c = 0; c < 5; c++) { acc0[c] = 0ull; acc1[c] = 0ull; acc2[c] = 0.f; }

    for (int ci = 0; ci < 33; ci++) {
        int chunk = ci * 2 + half;
        bool active = (chunk < NCHUNK_TOT);
        int pc = chunk * KC;
        __syncthreads();
        if (active) {
            const float4* src = (const float4*)&g_Apack[pc * APR];
#pragma unroll
            for (int q = 0; q < KC * APR / 4 / 256; q++) {
                int v = t + 256 * q;
                *(float4*)&At[v * 4] = src[v];
            }
#pragma unroll
            for (int q = 0; q < KC * FM / 256; q++) {
                int tt = t + 256 * q;
                int pl = tt / FM;
                int nd = tt - pl * FM;
                int p = pc + pl;
                int i = __ldg(&g_pi[p]);
                int j = __ldg(&g_pj[p]);
                Pt[pl * FM + nd] = hs[nd * 65 + i] * hs[nd * 65 + j];
            }
        }
        __syncthreads();
        if (active) {
#pragma unroll 4
            for (int kk = 0; kk < KC; kk++) {
                double2 pd = *(const double2*)&Pt[kk * FM + 4 * lane];
                float p4 = Pt[kk * FM + 128 + lane];
                ull_t p01 = __double_as_longlong(pd.x);
                ull_t p23 = __double_as_longlong(pd.y);
                const float* arow = At + kk * APR + kg * 12;
                double2 a01 = *(const double2*)arow;
                double2 a23 = *(const double2*)(arow + 4);
                ull_t a4 = *(const ull_t*)(arow + 8);
                ull_t a0 = __double_as_longlong(a01.x);
                ull_t a1 = __double_as_longlong(a01.y);
                ull_t a2 = __double_as_longlong(a23.x);
                ull_t a3 = __double_as_longlong(a23.y);
                float a0s = __uint_as_float((unsigned)(a0 & 0xffffffffull));
                float a1s = __uint_as_float((unsigned)(a1 & 0xffffffffull));
                float a2s = __uint_as_float((unsigned)(a2 & 0xffffffffull));
                float a3s = __uint_as_float((unsigned)(a3 & 0xffffffffull));
                float a4s = __uint_as_float((unsigned)(a4 & 0xffffffffull));
                FMA_F32X2(acc0[0], p01, a0, acc0[0]);
                FMA_F32X2(acc1[0], p23, a0, acc1[0]);
                acc2[0] = fmaf(p4, a0s, acc2[0]);
                FMA_F32X2(acc0[1], p01, a1, acc0[1]);
                FMA_F32X2(acc1[1], p23, a1, acc1[1]);
                acc2[1] = fmaf(p4, a1s, acc2[1]);
                FMA_F32X2(acc0[2], p01, a2, acc0[2]);
                FMA_F32X2(acc1[2], p23, a2, acc1[2]);
                acc2[2] = fmaf(p4, a2s, acc2[2]);
                FMA_F32X2(acc0[3], p01, a3, acc0[3]);
                FMA_F32X2(acc1[3], p23, a3, acc1[3]);
                acc2[3] = fmaf(p4, a3s, acc2[3]);
                FMA_F32X2(acc0[4], p01, a4, acc0[4]);
                FMA_F32X2(acc1[4], p23, a4, acc1[4]);
                acc2[4] = fmaf(p4, a4s, acc2[4]);
            }
        }
    }
    __syncthreads();

    float* zsh = smem + (half == 0 ? OFF_PT : OFF_H);
#pragma unroll
    for (int c = 0; c < 5; c++) {
        int k = kg * 5 + c;
        zsh[(4 * lane + 0) * C_OUT + k] = __uint_as_float((unsigned)(acc0[c] & 0xffffffffull));
        zsh[(4 * lane + 1) * C_OUT + k] = __uint_as_float((unsigned)(acc0[c] >> 32));
        zsh[(4 * lane + 2) * C_OUT + k] = __uint_as_float((unsigned)(acc1[c] & 0xffffffffull));
        zsh[(4 * lane + 3) * C_OUT + k] = __uint_as_float((unsigned)(acc1[c] >> 32));
        zsh[(128 + lane) * C_OUT + k]   = acc2[c];
    }
    __syncthreads();

    if (tid < FM) {
        int gn = n0 + tid;
        if (gn < N_NODES) {
            const float* zs0 = smem + OFF_PT;
            const float* zs1 = smem + OFF_H;
            const float MAXN = 1.0f - 4e-3f;
            float n2 = fmaxf(n2s[tid], 1e-15f);
            float pn = fminf(n2, MAXN);
            float tt = atanhf(pn);
            float scale = tt / n2;

            float u[C_OUT];
            float un2 = 0.f;
#pragma unroll
            for (int k = 0; k < C_OUT; k++) {
                float z = zs0[tid * C_OUT + k] + zs1[tid * C_OUT + k];
                float v = scale * z + b1[k];
                u[k] = v;
                un2 = fmaf(v, v, un2);
            }
            float un = fmaxf(sqrtf(un2), 1e-15f);
            float th = tanhf(un);
            float gsc = fminf(th, MAXN) / un;

            float m = -INFINITY;
#pragma unroll
            for (int k = 0; k < C_OUT; k++) {
                u[k] *= gsc;
                m = fmaxf(m, u[k]);
            }
            float se = 0.f;
#pragma unroll
            for (int k = 0; k < C_OUT; k++) se += expf(u[k] - m);
            float lse = m + logf(se);
#pragma unroll
            for (int k = 0; k < C_OUT; k++) out[gn * C_OUT + k] = u[k] - lse;
        }
    }
}

// ---------------- launch ----------------
// 1 hist(+pair init), 2 scan(+cnt reset), 3 fused scatter+lin0, 4 spmm0 <- profiled
extern "C" void kernel_launch(void* const* d_in, const int* in_sizes, int n_in,
                              void* d_out, int out_size) {
    const float* x      = (const float*)d_in[0];
    const int*   row    = (const int*)d_in[1];
    const int*   col    = (const int*)d_in[2];
    const float* ew     = (const float*)d_in[3];
    const float* lin0_w = (const float*)d_in[4];
    const float* lin0_b = (const float*)d_in[5];
    const float* conv_w = (const float*)d_in[6];
    const float* lin1_w = (const float*)d_in[7];
    const float* lin1_b = (const float*)d_in[8];
    float* out = (float*)d_out;

    float* hA = nullptr;
    float* hB = nullptr;
    float* tmp = nullptr;
    cudaGetSymbolAddress((void**)&hA, g_hA);
    cudaGetSymbolAddress((void**)&hB, g_hB);
    cudaGetSymbolAddress((void**)&tmp, g_tmp);

    cudaFuncSetAttribute(fused_scatter_lin0, cudaFuncAttributeMaxDynamicSharedMemorySize,
                         L0_SMEM_BYTES);
    cudaFuncSetAttribute(mixmm_kernel, cudaFuncAttributeMaxDynamicSharedMemorySize,
                         L0_SMEM_BYTES);
    cudaFuncSetAttribute(final_kernel, cudaFuncAttributeMaxDynamicSharedMemorySize,
                         FK_SMEM_BYTES);

    hist_kernel<<<(E_EDGES + 255) / 256, 256>>>(row);                       // 1
    scan_kernel<<<1, 1024>>>();                                             // 2
    fused_scatter_lin0<<<SC_BLOCKS + L0_BLOCKS, 512, L0_SMEM_BYTES>>>(
        row, col, ew, x, lin0_w, lin0_b);                                   // 3

    const float* hin = hA;
    float* hout = hB;
    {
        float beta = logf(0.5f / 1.0f + 1.0f);
        spmm_kernel<<<(N_NODES + 7) / 8, 256>>>(hin, tmp);                  // 4 <- profiled
        mixmm_kernel<<<L0_BLOCKS, 512, L0_SMEM_BYTES>>>(tmp, conv_w,
                                                        hout, 1.0f - beta, beta);
        const float* tp = hin; hin = hout; hout = (float*)tp;
    }
    apack_kernel<<<(NPAIR * C_OUT + 255) / 256, 256>>>(lin1_w);

    for (int l = 1; l < L_LAYERS; l++) {
        float beta = logf(0.5f / (float)(l + 1) + 1.0f);
        spmm_kernel<<<(N_NODES + 7) / 8, 256>>>(hin, tmp);
        mixmm_kernel<<<L0_BLOCKS, 512, L0_SMEM_BYTES>>>(tmp, conv_w + l * HDIM * HDIM,
                                                        hout, 1.0f - beta, beta);
        const float* tp = hin; hin = hout; hout = (float*)tp;
    }

    final_kernel<<<N_NODES / FM, FTHR, FK_SMEM_BYTES>>>(hin, lin1_b, out);
}